// round 11
// baseline (speedup 1.0000x reference)
#include <cuda_runtime.h>
#include <cuda_bf16.h>
#include <cstdint>

// ---------------------------------------------------------------------------
// RSSM rollout: H=16 steps, B=2048
// R10: R7 core (256 thr, 64x32 warp tile, bf16x3 RZ-safe) with the staged
//      register loads replaced by a 3-stage cp.async pipeline.
//      Math identical to R7 -> output bit-identical (rel_err 5.757308e-08).
// ---------------------------------------------------------------------------

#define B_       2048
#define DETER_   512
#define SC_      1024
#define ACT_     10
#define H_       16
#define KCAT     1552
#define OUTW     1536

#define KPAD     24
#define PLANE_ELT (128 * KPAD)
#define SMEM_HALF (6 * PLANE_ELT)          // one stage: A(3)+B(3) planes
#define NSTAGE   3
#define SMEM_BYTES (NSTAGE * SMEM_HALF * 2)   // 110592 B

// fp32 state
__device__ float g_deter[B_ * DETER_];
__device__ float g_rz[B_ * 1024];
__device__ float g_xn[B_ * DETER_];
__device__ float g_hn[B_ * DETER_];
__device__ float g_h1p[2 * B_ * DETER_];
__device__ float g_logits[B_ * SC_];

// bf16x3 planes
__device__ __nv_bfloat16 gW0[2048 * KCAT], gW1[2048 * KCAT], gW2[2048 * KCAT];
__device__ __nv_bfloat16 gX0[B_ * KCAT],  gX1[B_ * KCAT],  gX2[B_ * KCAT];
__device__ __nv_bfloat16 gD0[B_ * DETER_], gD1[B_ * DETER_], gD2[B_ * DETER_];
__device__ __nv_bfloat16 gH0[B_ * DETER_], gH1[B_ * DETER_], gH2[B_ * DETER_];
__device__ __nv_bfloat16 gP10[512 * 512],  gP11[512 * 512],  gP12[512 * 512];
__device__ __nv_bfloat16 gP20[1024 * 512], gP21[1024 * 512], gP22[1024 * 512];

// ---------------------------------------------------------------------------
// Threefry-2x32 (JAX schedule) — proven bit-exact, do not touch
// ---------------------------------------------------------------------------
__host__ __device__ __forceinline__ uint32_t rotl32(uint32_t v, int d) {
    return (v << d) | (v >> (32 - d));
}
__host__ __device__ __forceinline__ void threefry2x32(uint32_t k0, uint32_t k1,
                                                      uint32_t x0, uint32_t x1,
                                                      uint32_t& o0, uint32_t& o1) {
    uint32_t ks0 = k0, ks1 = k1, ks2 = k0 ^ k1 ^ 0x1BD11BDAu;
    x0 += ks0; x1 += ks1;
    x0 += x1; x1 = rotl32(x1, 13); x1 ^= x0;
    x0 += x1; x1 = rotl32(x1, 15); x1 ^= x0;
    x0 += x1; x1 = rotl32(x1, 26); x1 ^= x0;
    x0 += x1; x1 = rotl32(x1, 6);  x1 ^= x0;
    x0 += ks1; x1 += ks2 + 1u;
    x0 += x1; x1 = rotl32(x1, 17); x1 ^= x0;
    x0 += x1; x1 = rotl32(x1, 29); x1 ^= x0;
    x0 += x1; x1 = rotl32(x1, 16); x1 ^= x0;
    x0 += x1; x1 = rotl32(x1, 24); x1 ^= x0;
    x0 += ks2; x1 += ks0 + 2u;
    x0 += x1; x1 = rotl32(x1, 13); x1 ^= x0;
    x0 += x1; x1 = rotl32(x1, 15); x1 ^= x0;
    x0 += x1; x1 = rotl32(x1, 26); x1 ^= x0;
    x0 += x1; x1 = rotl32(x1, 6);  x1 ^= x0;
    x0 += ks0; x1 += ks1 + 3u;
    x0 += x1; x1 = rotl32(x1, 17); x1 ^= x0;
    x0 += x1; x1 = rotl32(x1, 29); x1 ^= x0;
    x0 += x1; x1 = rotl32(x1, 16); x1 ^= x0;
    x0 += x1; x1 = rotl32(x1, 24); x1 ^= x0;
    x0 += ks1; x1 += ks2 + 4u;
    x0 += x1; x1 = rotl32(x1, 13); x1 ^= x0;
    x0 += x1; x1 = rotl32(x1, 15); x1 ^= x0;
    x0 += x1; x1 = rotl32(x1, 26); x1 ^= x0;
    x0 += x1; x1 = rotl32(x1, 6);  x1 ^= x0;
    x0 += ks2; x1 += ks0 + 5u;
    o0 = x0; o1 = x1;
}

// exact 3-way bf16 split
__device__ __forceinline__ void split3(float v, __nv_bfloat16& b0,
                                       __nv_bfloat16& b1, __nv_bfloat16& b2) {
    b0 = __float2bfloat16_rn(v);
    float r = v - __bfloat162float(b0);
    b1 = __float2bfloat16_rn(r);
    float r2 = r - __bfloat162float(b1);
    b2 = __float2bfloat16_rn(r2);
}

// ---------------------------------------------------------------------------
// Prep kernels (one-time)
// ---------------------------------------------------------------------------
__global__ void init_kernel(const float* __restrict__ stoch0,
                            const float* __restrict__ act_seq,
                            const float* __restrict__ deter0) {
    int gid = blockIdx.x * blockDim.x + threadIdx.x;
    if (gid >= B_ * KCAT) return;
    int b = gid / KCAT, k = gid % KCAT;
    float v = 0.f;
    if (k < SC_)             v = stoch0[b * SC_ + k];
    else if (k < SC_ + ACT_) v = act_seq[b * ACT_ + (k - SC_)];
    else if (k < 1546)       v = deter0[b * DETER_ + (k - SC_ - ACT_)];
    split3(v, gX0[gid], gX1[gid], gX2[gid]);
    if (k < DETER_) {
        float d = deter0[b * DETER_ + k];
        g_deter[b * DETER_ + k] = d;
        split3(d, gD0[b * DETER_ + k], gD1[b * DETER_ + k], gD2[b * DETER_ + k]);
    }
}

__global__ void wprep_kernel(const float* __restrict__ W_ih,
                             const float* __restrict__ W_hh) {
    int gid = blockIdx.x * blockDim.x + threadIdx.x;
    if (gid >= 2048 * KCAT) return;
    int r = gid / KCAT, k = gid % KCAT;
    float v = 0.f;
    if (r < 1024) {
        if (k < 1034)       v = W_ih[r * 1034 + k];
        else if (k < 1546)  v = W_hh[r * 512 + (k - 1034)];
    } else if (r < 1536) {
        if (k < 1034)       v = W_ih[r * 1034 + k];
    } else {
        if (k >= 1034 && k < 1546) v = W_hh[(r - 512) * 512 + (k - 1034)];
    }
    split3(v, gW0[gid], gW1[gid], gW2[gid]);
}

__global__ void pprep_kernel(const float* __restrict__ pW1,
                             const float* __restrict__ pW2) {
    int gid = blockIdx.x * blockDim.x + threadIdx.x;
    if (gid < 512 * 512) {
        split3(pW1[gid], gP10[gid], gP11[gid], gP12[gid]);
    } else if (gid < 512 * 512 + 1024 * 512) {
        int i = gid - 512 * 512;
        split3(pW2[i], gP20[i], gP21[i], gP22[i]);
    }
}

// ---------------------------------------------------------------------------
// MMA / async-copy primitives
// ---------------------------------------------------------------------------
__device__ __forceinline__ void mma16816(float& c0, float& c1, float& c2, float& c3,
                                         uint32_t a0, uint32_t a1, uint32_t a2, uint32_t a3,
                                         uint32_t b0, uint32_t b1) {
    asm volatile(
        "mma.sync.aligned.m16n8k16.row.col.f32.bf16.bf16.f32 "
        "{%0,%1,%2,%3}, {%4,%5,%6,%7}, {%8,%9}, {%0,%1,%2,%3};"
        : "+f"(c0), "+f"(c1), "+f"(c2), "+f"(c3)
        : "r"(a0), "r"(a1), "r"(a2), "r"(a3), "r"(b0), "r"(b1));
}

__device__ __forceinline__ void ldm_x4(uint32_t& r0, uint32_t& r1,
                                       uint32_t& r2, uint32_t& r3, uint32_t addr) {
    asm volatile("ldmatrix.sync.aligned.m8n8.x4.shared.b16 {%0,%1,%2,%3}, [%4];"
                 : "=r"(r0), "=r"(r1), "=r"(r2), "=r"(r3) : "r"(addr));
}

__device__ __forceinline__ void cp16(uint32_t dst, const void* src) {
    asm volatile("cp.async.cg.shared.global [%0], [%1], 16;"
                 :: "r"(dst), "l"(src));
}
__device__ __forceinline__ void cp_commit() {
    asm volatile("cp.async.commit_group;");
}
__device__ __forceinline__ void cp_wait1() {
    asm volatile("cp.async.wait_group 1;");
}

// ---------------------------------------------------------------------------
// bf16x3 MMA core (256 threads, 2x4 warps, 64x32 warp tile), 3-stage cp.async.
// corr_klo: k below which A planes 1/2 are exactly zero (skipped — exact).
// ---------------------------------------------------------------------------
__device__ __forceinline__ void mma_core(
    const __nv_bfloat16* __restrict__ A0, const __nv_bfloat16* __restrict__ A1,
    const __nv_bfloat16* __restrict__ A2, int lda,
    const __nv_bfloat16* __restrict__ B0, const __nv_bfloat16* __restrict__ B1,
    const __nv_bfloat16* __restrict__ B2, int ldb,
    int klo, int khi, int corr_klo, int bm, int bn,
    float (&accM)[4][4][4], float (&accC)[4][4][4]) {
    extern __shared__ __nv_bfloat16 sm[];
    const int tid = threadIdx.x;
    const int lane = tid & 31;
    const int wm = ((tid >> 5) >> 2) * 64;
    const int wn = ((tid >> 5) & 3) * 32;
    const int g = lane >> 2, tig = lane & 3;
    const int lrow = tid >> 1, lhalf = tid & 1;

    const uint32_t smbase = (uint32_t)__cvta_generic_to_shared(sm);
    const int nk = (khi - klo) >> 4;

    // per-thread copy target: one 16B chunk per plane at (lrow, lhalf)
    const __nv_bfloat16* planes[6] = {
        A0 + (size_t)(bm + lrow) * lda + lhalf * 8,
        A1 + (size_t)(bm + lrow) * lda + lhalf * 8,
        A2 + (size_t)(bm + lrow) * lda + lhalf * 8,
        B0 + (size_t)(bn + lrow) * ldb + lhalf * 8,
        B1 + (size_t)(bn + lrow) * ldb + lhalf * 8,
        B2 + (size_t)(bn + lrow) * ldb + lhalf * 8};
    const uint32_t dst_off = (uint32_t)((lrow * KPAD + lhalf * 8) * 2);

    bool corrbuf[NSTAGE] = {false, false, false};

    // issue one stage (always commits a group, possibly empty)
    auto issue_slab = [&](int buf, int k0, bool valid) {
        if (valid) {
            const bool gf = (k0 >= corr_klo);
            const uint32_t base = smbase + (uint32_t)(buf * SMEM_HALF) * 2;
            cp16(base + 0 * PLANE_ELT * 2 + dst_off, planes[0] + k0);
            if (gf) {
                cp16(base + 1 * PLANE_ELT * 2 + dst_off, planes[1] + k0);
                cp16(base + 2 * PLANE_ELT * 2 + dst_off, planes[2] + k0);
            }
            cp16(base + 3 * PLANE_ELT * 2 + dst_off, planes[3] + k0);
            cp16(base + 4 * PLANE_ELT * 2 + dst_off, planes[4] + k0);
            cp16(base + 5 * PLANE_ELT * 2 + dst_off, planes[5] + k0);
            corrbuf[buf] = gf;
        }
        cp_commit();
    };

    auto compute = [&](int buf) {
        const bool corr = corrbuf[buf];
        const uint32_t abase = smbase + (uint32_t)(buf * SMEM_HALF) * 2;
        const __nv_bfloat16* sbb = sm + buf * SMEM_HALF + 3 * PLANE_ELT;
        uint32_t bf[3][4][2];
#pragma unroll
        for (int nt = 0; nt < 4; nt++) {
            const __nv_bfloat16* bq = sbb + (wn + nt * 8 + g) * KPAD + 2 * tig;
#pragma unroll
            for (int p = 0; p < 3; p++) {
                bf[p][nt][0] = *(const uint32_t*)(bq + p * PLANE_ELT);
                bf[p][nt][1] = *(const uint32_t*)(bq + p * PLANE_ELT + 8);
            }
        }
#pragma unroll
        for (int mt = 0; mt < 4; mt++) {
            uint32_t a0f[4], a1f[4], a2f[4];
            uint32_t arow = (uint32_t)((wm + mt * 16 + (lane & 15)) * KPAD * 2) +
                            (uint32_t)((lane >> 4) * 16);
            ldm_x4(a0f[0], a0f[1], a0f[2], a0f[3], abase + 0 * PLANE_ELT * 2 + arow);
            if (corr) {
                ldm_x4(a1f[0], a1f[1], a1f[2], a1f[3], abase + 1 * PLANE_ELT * 2 + arow);
                ldm_x4(a2f[0], a2f[1], a2f[2], a2f[3], abase + 2 * PLANE_ELT * 2 + arow);
            }
#pragma unroll
            for (int nt = 0; nt < 4; nt++) {
                // main product: fresh C=0, RN FADD flush
                float p0 = 0.f, p1 = 0.f, p2 = 0.f, p3 = 0.f;
                mma16816(p0, p1, p2, p3,
                         a0f[0], a0f[1], a0f[2], a0f[3],
                         bf[0][nt][0], bf[0][nt][1]);
                accM[mt][nt][0] += p0;
                accM[mt][nt][1] += p1;
                accM[mt][nt][2] += p2;
                accM[mt][nt][3] += p3;
                // corrections, chained in TC, small -> large
                float* c = accC[mt][nt];
                if (corr) {
                    mma16816(c[0], c[1], c[2], c[3],
                             a2f[0], a2f[1], a2f[2], a2f[3],
                             bf[0][nt][0], bf[0][nt][1]);
                    mma16816(c[0], c[1], c[2], c[3],
                             a1f[0], a1f[1], a1f[2], a1f[3],
                             bf[1][nt][0], bf[1][nt][1]);
                }
                mma16816(c[0], c[1], c[2], c[3],
                         a0f[0], a0f[1], a0f[2], a0f[3],
                         bf[2][nt][0], bf[2][nt][1]);
                if (corr) {
                    mma16816(c[0], c[1], c[2], c[3],
                             a1f[0], a1f[1], a1f[2], a1f[3],
                             bf[0][nt][0], bf[0][nt][1]);
                }
                mma16816(c[0], c[1], c[2], c[3],
                         a0f[0], a0f[1], a0f[2], a0f[3],
                         bf[1][nt][0], bf[1][nt][1]);
            }
        }
    };

    // prologue: stages 0 and 1 in flight; wait for stage 0 (all but newest)
    issue_slab(0, klo, true);
    issue_slab(1, klo + 16, nk > 1);
    cp_wait1();
    __syncthreads();

    for (int it = 0; it < nk; it++) {
        compute(it % NSTAGE);
        issue_slab((it + 2) % NSTAGE, klo + (it + 2) * 16, it + 2 < nk);
        cp_wait1();             // all groups except newest complete -> stage it+1 ready
        __syncthreads();        // also fences buffer (it+2)%3 reuse
    }
}

#define EPI_LOOP(body)                                                        \
    {                                                                         \
        const int lane = threadIdx.x & 31;                                    \
        const int wm = ((threadIdx.x >> 5) >> 2) * 64;                        \
        const int wn = ((threadIdx.x >> 5) & 3) * 32;                         \
        const int g = lane >> 2, tig = lane & 3;                              \
        _Pragma("unroll") for (int mt = 0; mt < 4; mt++)                      \
            _Pragma("unroll") for (int nt = 0; nt < 4; nt++) {                \
            int m0 = bm + wm + mt * 16 + g;                                   \
            int n0 = bn + wn + nt * 8 + 2 * tig;                              \
            float v0 = accC[mt][nt][0] + accM[mt][nt][0];                     \
            float v1 = accC[mt][nt][1] + accM[mt][nt][1];                     \
            float v2 = accC[mt][nt][2] + accM[mt][nt][2];                     \
            float v3 = accC[mt][nt][3] + accM[mt][nt][3];                     \
            body                                                              \
        }                                                                     \
    }

// ---------------------------------------------------------------------------
// GRU GEMM: 1D grid, heavy-first order. corr_klo=1024 (stoch onehot).
// ---------------------------------------------------------------------------
__global__ void __launch_bounds__(256) gru_mma(const float* __restrict__ b_ih,
                                               const float* __restrict__ b_hh) {
    float accM[4][4][4] = {}, accC[4][4][4] = {};
    int bid = blockIdx.x;
    int bmT, bnT;
    if (bid < 128)      { bnT = bid & 7;             bmT = bid >> 3; }
    else if (bid < 192) { int r = bid - 128; bnT = 8 + (r & 3);  bmT = r >> 2; }
    else                { int r = bid - 192; bnT = 12 + (r & 3); bmT = r >> 2; }
    int bm = bmT * 128, bn = bnT * 128;
    int klo, khi;
    if (bnT < 8)       { klo = 0;    khi = KCAT; }
    else if (bnT < 12) { klo = 0;    khi = 1040; }
    else               { klo = 1024; khi = KCAT; }
    mma_core(gX0, gX1, gX2, KCAT, gW0, gW1, gW2, KCAT,
             klo, khi, 1024, bm, bn, accM, accC);

    auto wr = [&](int m, int n, float v) {
        if (n < 1024)      g_rz[m * 1024 + n] = v + b_ih[n] + b_hh[n];
        else if (n < 1536) g_xn[m * 512 + (n - 1024)] = v + b_ih[n];
        else               g_hn[m * 512 + (n - 1536)] = v + b_hh[(n - 1536) + 1024];
    };
    EPI_LOOP({
        wr(m0, n0, v0);
        wr(m0, n0 + 1, v1);
        wr(m0 + 8, n0, v2);
        wr(m0 + 8, n0 + 1, v3);
    })
}

// b1: split-K=2, partials (no bias) -> g_h1p[z]
__global__ void __launch_bounds__(256) b1_mma() {
    float accM[4][4][4] = {}, accC[4][4][4] = {};
    int bm = blockIdx.y * 128, bn = blockIdx.x * 128;
    int z = blockIdx.z;
    mma_core(gD0, gD1, gD2, 512, gP10, gP11, gP12, 512,
             z * 256, (z + 1) * 256, 0, bm, bn, accM, accC);
    float* dst = g_h1p + (size_t)z * B_ * 512;
    EPI_LOOP({
        dst[m0 * 512 + n0]           = v0;
        dst[m0 * 512 + n0 + 1]       = v1;
        dst[(m0 + 8) * 512 + n0]     = v2;
        dst[(m0 + 8) * 512 + n0 + 1] = v3;
    })
}

__global__ void __launch_bounds__(256) c_mma(const float* __restrict__ pb2) {
    float accM[4][4][4] = {}, accC[4][4][4] = {};
    int bm = blockIdx.y * 128, bn = blockIdx.x * 128;
    mma_core(gH0, gH1, gH2, 512, gP20, gP21, gP22, 512,
             0, 512, 0, bm, bn, accM, accC);
    EPI_LOOP({
        g_logits[m0 * 1024 + n0]           = v0 + pb2[n0];
        g_logits[m0 * 1024 + n0 + 1]       = v1 + pb2[n0 + 1];
        g_logits[(m0 + 8) * 1024 + n0]     = v2 + pb2[n0];
        g_logits[(m0 + 8) * 1024 + n0 + 1] = v3 + pb2[n0 + 1];
    })
}

// ---------------------------------------------------------------------------
// GRU gates
// ---------------------------------------------------------------------------
__global__ void gates_kernel(float* __restrict__ out, int t) {
    int gid = blockIdx.x * blockDim.x + threadIdx.x;
    int b = gid >> 9, d = gid & 511;
    float sr = g_rz[b * 1024 + d];
    float sz = g_rz[b * 1024 + 512 + d];
    float xn = g_xn[b * 512 + d];
    float hn = g_hn[b * 512 + d];
    float h  = g_deter[b * 512 + d];
    float r = 1.f / (1.f + expf(-sr));
    float z = 1.f / (1.f + expf(-sz));
    float n = tanhf(xn + r * hn);
    float dn = (1.f - z) * n + z * h;
    g_deter[b * 512 + d] = dn;
    out[((size_t)t * B_ + b) * OUTW + d] = dn;
    __nv_bfloat16 p0, p1, p2;
    split3(dn, p0, p1, p2);
    int xk = b * KCAT + 1034 + d;
    gX0[xk] = p0; gX1[xk] = p1; gX2[xk] = p2;
    int dk = b * 512 + d;
    gD0[dk] = p0; gD1[dk] = p1; gD2[dk] = p2;
}

// ---------------------------------------------------------------------------
// LayerNorm + SiLU; sums split-K partials + bias (fixed RN order)
// ---------------------------------------------------------------------------
__global__ void ln_kernel(const float* __restrict__ pg,
                          const float* __restrict__ pbeta,
                          const float* __restrict__ pb1) {
    __shared__ float red[256];
    int b = blockIdx.x, tid = threadIdx.x;
    const float* x0 = g_h1p + b * 512;
    const float* x1 = g_h1p + (size_t)B_ * 512 + b * 512;
    float v0 = (x0[tid] + x1[tid]) + pb1[tid];
    float v1 = (x0[tid + 256] + x1[tid + 256]) + pb1[tid + 256];
    red[tid] = v0 + v1;
    __syncthreads();
    for (int s = 128; s > 0; s >>= 1) {
        if (tid < s) red[tid] += red[tid + s];
        __syncthreads();
    }
    float mean = red[0] * (1.f / 512.f);
    __syncthreads();
    float d0 = v0 - mean, d1 = v1 - mean;
    red[tid] = d0 * d0 + d1 * d1;
    __syncthreads();
    for (int s = 128; s > 0; s >>= 1) {
        if (tid < s) red[tid] += red[tid + s];
        __syncthreads();
    }
    float var = red[0] * (1.f / 512.f);
    float rstd = rsqrtf(var + 1e-5f);
    float y0 = d0 * rstd * pg[tid] + pbeta[tid];
    float y1 = d1 * rstd * pg[tid + 256] + pbeta[tid + 256];
    float s0 = y0 * (1.f / (1.f + expf(-y0)));
    float s1 = y1 * (1.f / (1.f + expf(-y1)));
    __nv_bfloat16 a, bb, c;
    split3(s0, a, bb, c);
    gH0[b * 512 + tid] = a; gH1[b * 512 + tid] = bb; gH2[b * 512 + tid] = c;
    split3(s1, a, bb, c);
    gH0[b * 512 + tid + 256] = a; gH1[b * 512 + tid + 256] = bb; gH2[b * 512 + tid + 256] = c;
}

// ---------------------------------------------------------------------------
// Gumbel-max sampling
// ---------------------------------------------------------------------------
__global__ void sample_kernel(const float* __restrict__ act_seq,
                              float* __restrict__ out,
                              int t, uint32_t k0, uint32_t k1) {
    int gid = blockIdx.x * blockDim.x + threadIdx.x;
    int b = gid >> 5, s = gid & 31;
    const float* lg = g_logits + b * 1024 + s * 32;
    float best = -1e30f;
    int bi = 0;
#pragma unroll 4
    for (int c = 0; c < 32; c++) {
        uint32_t idx = (uint32_t)(b * 1024 + s * 32 + c);
        uint32_t o0, o1;
        threefry2x32(k0, k1, 0u, idx, o0, o1);
        uint32_t bits = o0 ^ o1;
        float u = __uint_as_float((bits >> 9) | 0x3f800000u) - 1.0f;
        u = fmaxf(u, 1.1754943508222875e-38f);
        float g = -logf(-logf(u));
        float v = g + lg[c];
        if (v > best) { best = v; bi = c; }
    }
    const __nv_bfloat16 zero = __float2bfloat16_rn(0.f);
    const __nv_bfloat16 one  = __float2bfloat16_rn(1.f);
    int xbase = b * KCAT + s * 32;
    float* os = out + ((size_t)t * B_ + b) * OUTW + 512 + s * 32;
#pragma unroll
    for (int c = 0; c < 32; c++) {
        bool hit = (c == bi);
        os[c] = hit ? 1.0f : 0.0f;
        gX0[xbase + c] = hit ? one : zero;
        gX1[xbase + c] = zero;
        gX2[xbase + c] = zero;
    }
    if (t < H_ - 1 && s < ACT_) {
        float a = act_seq[(((size_t)(t + 1)) * B_ + b) * ACT_ + s];
        __nv_bfloat16 p0, p1, p2;
        split3(a, p0, p1, p2);
        int ak = b * KCAT + SC_ + s;
        gX0[ak] = p0; gX1[ak] = p1; gX2[ak] = p2;
    }
}

// ---------------------------------------------------------------------------
// Host launcher
// ---------------------------------------------------------------------------
extern "C" void kernel_launch(void* const* d_in, const int* in_sizes, int n_in,
                              void* d_out, int out_size) {
    const float* act    = (const float*)d_in[0];
    const float* deter0 = (const float*)d_in[1];
    const float* stoch0 = (const float*)d_in[2];
    const float* W_ih   = (const float*)d_in[3];
    const float* b_ih   = (const float*)d_in[4];
    const float* W_hh   = (const float*)d_in[5];
    const float* b_hh   = (const float*)d_in[6];
    const float* pW1    = (const float*)d_in[7];
    const float* pb1    = (const float*)d_in[8];
    const float* pg     = (const float*)d_in[9];
    const float* pbeta  = (const float*)d_in[10];
    const float* pW2    = (const float*)d_in[11];
    const float* pb2    = (const float*)d_in[12];
    float* out = (float*)d_out;

    uint32_t keys[H_][2];
    for (int t = 0; t < H_; t++) {
        uint32_t o0, o1;
        threefry2x32(0u, 42u, 0u, (uint32_t)t, o0, o1);
        keys[t][0] = o0;
        keys[t][1] = o1;
    }

    cudaFuncSetAttribute(gru_mma, cudaFuncAttributeMaxDynamicSharedMemorySize, SMEM_BYTES);
    cudaFuncSetAttribute(b1_mma,  cudaFuncAttributeMaxDynamicSharedMemorySize, SMEM_BYTES);
    cudaFuncSetAttribute(c_mma,   cudaFuncAttributeMaxDynamicSharedMemorySize, SMEM_BYTES);

    cudaStream_t st = cudaStreamPerThread;
    init_kernel<<<(B_ * KCAT + 255) / 256, 256, 0, st>>>(stoch0, act, deter0);
    wprep_kernel<<<(2048 * KCAT + 255) / 256, 256, 0, st>>>(W_ih, W_hh);
    pprep_kernel<<<((512 * 512 + 1024 * 512) + 255) / 256, 256, 0, st>>>(pW1, pW2);

    for (int t = 0; t < H_; t++) {
        gru_mma<<<256, 256, SMEM_BYTES, st>>>(b_ih, b_hh);
        gates_kernel<<<(B_ * DETER_) / 256, 256, 0, st>>>(out, t);
        b1_mma<<<dim3(4, 16, 2), 256, SMEM_BYTES, st>>>();
        ln_kernel<<<B_, 256, 0, st>>>(pg, pbeta, pb1);
        c_mma<<<dim3(8, 16), 256, SMEM_BYTES, st>>>(pb2);
        sample_kernel<<<(B_ * 32) / 128, 128, 0, st>>>(act, out, t, keys[t][0], keys[t][1]);
    }
}

// round 12
// speedup vs baseline: 2.0183x; 2.0183x over previous
#include <cuda_runtime.h>
#include <cuda_bf16.h>
#include <cstdint>

// ---------------------------------------------------------------------------
// RSSM rollout: H=16 steps, B=2048
// R11: exact R7 mma core (5418us baseline, untouched) +
//   - Gumbel noise precomputed once into g_gum (bit-identical threefry/logf)
//   - argmax sampling fused into c_mma epilogue (quad shuffle reduction,
//     first-max tie-break == jnp.argmax); sample_kernel + g_logits deleted
//   - next-step action staging moved into gates_kernel
// ---------------------------------------------------------------------------

#define B_       2048
#define DETER_   512
#define SC_      1024
#define ACT_     10
#define H_       16
#define KCAT     1552
#define OUTW     1536

#define KPAD     24
#define PLANE_ELT (128 * KPAD)
#define SMEM_HALF (6 * PLANE_ELT)
#define SMEM_BYTES (2 * SMEM_HALF * 2)   // 73728 B

// fp32 state
__device__ float g_deter[B_ * DETER_];
__device__ float g_rz[B_ * 1024];
__device__ float g_xn[B_ * DETER_];
__device__ float g_hn[B_ * DETER_];
__device__ float g_h1p[2 * B_ * DETER_];
__device__ float g_gum[(size_t)H_ * B_ * SC_];   // 134MB gumbel table

// bf16x3 planes
__device__ __nv_bfloat16 gW0[2048 * KCAT], gW1[2048 * KCAT], gW2[2048 * KCAT];
__device__ __nv_bfloat16 gX0[B_ * KCAT],  gX1[B_ * KCAT],  gX2[B_ * KCAT];
__device__ __nv_bfloat16 gD0[B_ * DETER_], gD1[B_ * DETER_], gD2[B_ * DETER_];
__device__ __nv_bfloat16 gH0[B_ * DETER_], gH1[B_ * DETER_], gH2[B_ * DETER_];
__device__ __nv_bfloat16 gP10[512 * 512],  gP11[512 * 512],  gP12[512 * 512];
__device__ __nv_bfloat16 gP20[1024 * 512], gP21[1024 * 512], gP22[1024 * 512];

// ---------------------------------------------------------------------------
// Threefry-2x32 (JAX schedule) — proven bit-exact, do not touch
// ---------------------------------------------------------------------------
__host__ __device__ __forceinline__ uint32_t rotl32(uint32_t v, int d) {
    return (v << d) | (v >> (32 - d));
}
__host__ __device__ __forceinline__ void threefry2x32(uint32_t k0, uint32_t k1,
                                                      uint32_t x0, uint32_t x1,
                                                      uint32_t& o0, uint32_t& o1) {
    uint32_t ks0 = k0, ks1 = k1, ks2 = k0 ^ k1 ^ 0x1BD11BDAu;
    x0 += ks0; x1 += ks1;
    x0 += x1; x1 = rotl32(x1, 13); x1 ^= x0;
    x0 += x1; x1 = rotl32(x1, 15); x1 ^= x0;
    x0 += x1; x1 = rotl32(x1, 26); x1 ^= x0;
    x0 += x1; x1 = rotl32(x1, 6);  x1 ^= x0;
    x0 += ks1; x1 += ks2 + 1u;
    x0 += x1; x1 = rotl32(x1, 17); x1 ^= x0;
    x0 += x1; x1 = rotl32(x1, 29); x1 ^= x0;
    x0 += x1; x1 = rotl32(x1, 16); x1 ^= x0;
    x0 += x1; x1 = rotl32(x1, 24); x1 ^= x0;
    x0 += ks2; x1 += ks0 + 2u;
    x0 += x1; x1 = rotl32(x1, 13); x1 ^= x0;
    x0 += x1; x1 = rotl32(x1, 15); x1 ^= x0;
    x0 += x1; x1 = rotl32(x1, 26); x1 ^= x0;
    x0 += x1; x1 = rotl32(x1, 6);  x1 ^= x0;
    x0 += ks0; x1 += ks1 + 3u;
    x0 += x1; x1 = rotl32(x1, 17); x1 ^= x0;
    x0 += x1; x1 = rotl32(x1, 29); x1 ^= x0;
    x0 += x1; x1 = rotl32(x1, 16); x1 ^= x0;
    x0 += x1; x1 = rotl32(x1, 24); x1 ^= x0;
    x0 += ks1; x1 += ks2 + 4u;
    x0 += x1; x1 = rotl32(x1, 13); x1 ^= x0;
    x0 += x1; x1 = rotl32(x1, 15); x1 ^= x0;
    x0 += x1; x1 = rotl32(x1, 26); x1 ^= x0;
    x0 += x1; x1 = rotl32(x1, 6);  x1 ^= x0;
    x0 += ks2; x1 += ks0 + 5u;
    o0 = x0; o1 = x1;
}

// exact 3-way bf16 split
__device__ __forceinline__ void split3(float v, __nv_bfloat16& b0,
                                       __nv_bfloat16& b1, __nv_bfloat16& b2) {
    b0 = __float2bfloat16_rn(v);
    float r = v - __bfloat162float(b0);
    b1 = __float2bfloat16_rn(r);
    float r2 = r - __bfloat162float(b1);
    b2 = __float2bfloat16_rn(r2);
}

// ---------------------------------------------------------------------------
// Prep kernels (one-time)
// ---------------------------------------------------------------------------
__global__ void init_kernel(const float* __restrict__ stoch0,
                            const float* __restrict__ act_seq,
                            const float* __restrict__ deter0) {
    int gid = blockIdx.x * blockDim.x + threadIdx.x;
    if (gid >= B_ * KCAT) return;
    int b = gid / KCAT, k = gid % KCAT;
    float v = 0.f;
    if (k < SC_)             v = stoch0[b * SC_ + k];
    else if (k < SC_ + ACT_) v = act_seq[b * ACT_ + (k - SC_)];
    else if (k < 1546)       v = deter0[b * DETER_ + (k - SC_ - ACT_)];
    split3(v, gX0[gid], gX1[gid], gX2[gid]);
    if (k < DETER_) {
        float d = deter0[b * DETER_ + k];
        g_deter[b * DETER_ + k] = d;
        split3(d, gD0[b * DETER_ + k], gD1[b * DETER_ + k], gD2[b * DETER_ + k]);
    }
}

__global__ void wprep_kernel(const float* __restrict__ W_ih,
                             const float* __restrict__ W_hh) {
    int gid = blockIdx.x * blockDim.x + threadIdx.x;
    if (gid >= 2048 * KCAT) return;
    int r = gid / KCAT, k = gid % KCAT;
    float v = 0.f;
    if (r < 1024) {
        if (k < 1034)       v = W_ih[r * 1034 + k];
        else if (k < 1546)  v = W_hh[r * 512 + (k - 1034)];
    } else if (r < 1536) {
        if (k < 1034)       v = W_ih[r * 1034 + k];
    } else {
        if (k >= 1034 && k < 1546) v = W_hh[(r - 512) * 512 + (k - 1034)];
    }
    split3(v, gW0[gid], gW1[gid], gW2[gid]);
}

__global__ void pprep_kernel(const float* __restrict__ pW1,
                             const float* __restrict__ pW2) {
    int gid = blockIdx.x * blockDim.x + threadIdx.x;
    if (gid < 512 * 512) {
        split3(pW1[gid], gP10[gid], gP11[gid], gP12[gid]);
    } else if (gid < 512 * 512 + 1024 * 512) {
        int i = gid - 512 * 512;
        split3(pW2[i], gP20[i], gP21[i], gP22[i]);
    }
}

// gumbel table: g_gum[t * 2^21 + idx] for idx = b*1024 + n (bit-identical to
// the per-step computation used by the proven sample path)
__global__ void gumbel_prep() {
    size_t gid = (size_t)blockIdx.x * blockDim.x + threadIdx.x;
    if (gid >= (size_t)H_ * B_ * SC_) return;
    uint32_t t = (uint32_t)(gid >> 21);
    uint32_t idx = (uint32_t)(gid & 0x1FFFFFu);
    uint32_t k0, k1, o0, o1;
    threefry2x32(0u, 42u, 0u, t, k0, k1);
    threefry2x32(k0, k1, 0u, idx, o0, o1);
    uint32_t bits = o0 ^ o1;
    float u = __uint_as_float((bits >> 9) | 0x3f800000u) - 1.0f;
    u = fmaxf(u, 1.1754943508222875e-38f);
    g_gum[gid] = -logf(-logf(u));
}

// ---------------------------------------------------------------------------
// MMA primitives
// ---------------------------------------------------------------------------
__device__ __forceinline__ void mma16816(float& c0, float& c1, float& c2, float& c3,
                                         uint32_t a0, uint32_t a1, uint32_t a2, uint32_t a3,
                                         uint32_t b0, uint32_t b1) {
    asm volatile(
        "mma.sync.aligned.m16n8k16.row.col.f32.bf16.bf16.f32 "
        "{%0,%1,%2,%3}, {%4,%5,%6,%7}, {%8,%9}, {%0,%1,%2,%3};"
        : "+f"(c0), "+f"(c1), "+f"(c2), "+f"(c3)
        : "r"(a0), "r"(a1), "r"(a2), "r"(a3), "r"(b0), "r"(b1));
}

__device__ __forceinline__ void ldm_x4(uint32_t& r0, uint32_t& r1,
                                       uint32_t& r2, uint32_t& r3, uint32_t addr) {
    asm volatile("ldmatrix.sync.aligned.m8n8.x4.shared.b16 {%0,%1,%2,%3}, [%4];"
                 : "=r"(r0), "=r"(r1), "=r"(r2), "=r"(r3) : "r"(addr));
}

// ---------------------------------------------------------------------------
// bf16x3 MMA core — EXACT R7 version (the 5418us winner). Do not touch.
// ---------------------------------------------------------------------------
__device__ __forceinline__ void mma_core(
    const __nv_bfloat16* __restrict__ A0, const __nv_bfloat16* __restrict__ A1,
    const __nv_bfloat16* __restrict__ A2, int lda,
    const __nv_bfloat16* __restrict__ B0, const __nv_bfloat16* __restrict__ B1,
    const __nv_bfloat16* __restrict__ B2, int ldb,
    int klo, int khi, int corr_klo, int bm, int bn,
    float (&accM)[4][4][4], float (&accC)[4][4][4]) {
    extern __shared__ __nv_bfloat16 sm[];
    const int tid = threadIdx.x;
    const int lane = tid & 31;
    const int wm = ((tid >> 5) >> 2) * 64;
    const int wn = ((tid >> 5) & 3) * 32;
    const int g = lane >> 2, tig = lane & 3;
    const int lrow = tid >> 1, lhalf = tid & 1;

    const __nv_bfloat16* Ap[3] = {
        A0 + (size_t)(bm + lrow) * lda + lhalf * 8,
        A1 + (size_t)(bm + lrow) * lda + lhalf * 8,
        A2 + (size_t)(bm + lrow) * lda + lhalf * 8};
    const __nv_bfloat16* Bp[3] = {
        B0 + (size_t)(bn + lrow) * ldb + lhalf * 8,
        B1 + (size_t)(bn + lrow) * ldb + lhalf * 8,
        B2 + (size_t)(bn + lrow) * ldb + lhalf * 8};

    const uint32_t smbase = (uint32_t)__cvta_generic_to_shared(sm);
    const int nk = (khi - klo) >> 4;
    const int st_off = lrow * KPAD + lhalf * 8;

    uint4 pa[3], pb[3];
    bool gf = false;
    bool corrbuf[2] = {false, false};

    auto gload = [&](int k0) {
        gf = (k0 >= corr_klo);
        pa[0] = *(const uint4*)(Ap[0] + k0);
#pragma unroll
        for (int p = 0; p < 3; p++) pb[p] = *(const uint4*)(Bp[p] + k0);
        if (gf) {
            pa[1] = *(const uint4*)(Ap[1] + k0);
            pa[2] = *(const uint4*)(Ap[2] + k0);
        }
    };
    auto sstore = [&](int buf) {
        __nv_bfloat16* base = sm + buf * SMEM_HALF;
        *(uint4*)(base + 0 * PLANE_ELT + st_off) = pa[0];
#pragma unroll
        for (int p = 0; p < 3; p++)
            *(uint4*)(base + (3 + p) * PLANE_ELT + st_off) = pb[p];
        if (gf) {
            *(uint4*)(base + 1 * PLANE_ELT + st_off) = pa[1];
            *(uint4*)(base + 2 * PLANE_ELT + st_off) = pa[2];
        }
        corrbuf[buf] = gf;
    };
    auto compute = [&](int buf) {
        const bool corr = corrbuf[buf];
        const uint32_t abase = smbase + (uint32_t)(buf * SMEM_HALF) * 2;
        const __nv_bfloat16* sbb = sm + buf * SMEM_HALF + 3 * PLANE_ELT;
        uint32_t bf[3][4][2];
#pragma unroll
        for (int nt = 0; nt < 4; nt++) {
            const __nv_bfloat16* bq = sbb + (wn + nt * 8 + g) * KPAD + 2 * tig;
#pragma unroll
            for (int p = 0; p < 3; p++) {
                bf[p][nt][0] = *(const uint32_t*)(bq + p * PLANE_ELT);
                bf[p][nt][1] = *(const uint32_t*)(bq + p * PLANE_ELT + 8);
            }
        }
#pragma unroll
        for (int mt = 0; mt < 4; mt++) {
            uint32_t a0f[4], a1f[4], a2f[4];
            uint32_t arow = (uint32_t)((wm + mt * 16 + (lane & 15)) * KPAD * 2) +
                            (uint32_t)((lane >> 4) * 16);
            ldm_x4(a0f[0], a0f[1], a0f[2], a0f[3], abase + 0 * PLANE_ELT * 2 + arow);
            if (corr) {
                ldm_x4(a1f[0], a1f[1], a1f[2], a1f[3], abase + 1 * PLANE_ELT * 2 + arow);
                ldm_x4(a2f[0], a2f[1], a2f[2], a2f[3], abase + 2 * PLANE_ELT * 2 + arow);
            }
#pragma unroll
            for (int nt = 0; nt < 4; nt++) {
                float p0 = 0.f, p1 = 0.f, p2 = 0.f, p3 = 0.f;
                mma16816(p0, p1, p2, p3,
                         a0f[0], a0f[1], a0f[2], a0f[3],
                         bf[0][nt][0], bf[0][nt][1]);
                accM[mt][nt][0] += p0;
                accM[mt][nt][1] += p1;
                accM[mt][nt][2] += p2;
                accM[mt][nt][3] += p3;
                float* c = accC[mt][nt];
                if (corr) {
                    mma16816(c[0], c[1], c[2], c[3],
                             a2f[0], a2f[1], a2f[2], a2f[3],
                             bf[0][nt][0], bf[0][nt][1]);
                    mma16816(c[0], c[1], c[2], c[3],
                             a1f[0], a1f[1], a1f[2], a1f[3],
                             bf[1][nt][0], bf[1][nt][1]);
                }
                mma16816(c[0], c[1], c[2], c[3],
                         a0f[0], a0f[1], a0f[2], a0f[3],
                         bf[2][nt][0], bf[2][nt][1]);
                if (corr) {
                    mma16816(c[0], c[1], c[2], c[3],
                             a1f[0], a1f[1], a1f[2], a1f[3],
                             bf[0][nt][0], bf[0][nt][1]);
                }
                mma16816(c[0], c[1], c[2], c[3],
                         a0f[0], a0f[1], a0f[2], a0f[3],
                         bf[1][nt][0], bf[1][nt][1]);
            }
        }
    };

    gload(klo);
    sstore(0);
    __syncthreads();
    int cur = 0;
    for (int it = 1; it < nk; it++) {
        gload(klo + it * 16);
        compute(cur);
        sstore(cur ^ 1);
        __syncthreads();
        cur ^= 1;
    }
    compute(cur);
}

#define EPI_LOOP(body)                                                        \
    {                                                                         \
        const int lane = threadIdx.x & 31;                                    \
        const int wm = ((threadIdx.x >> 5) >> 2) * 64;                        \
        const int wn = ((threadIdx.x >> 5) & 3) * 32;                         \
        const int g = lane >> 2, tig = lane & 3;                              \
        _Pragma("unroll") for (int mt = 0; mt < 4; mt++)                      \
            _Pragma("unroll") for (int nt = 0; nt < 4; nt++) {                \
            int m0 = bm + wm + mt * 16 + g;                                   \
            int n0 = bn + wn + nt * 8 + 2 * tig;                              \
            float v0 = accC[mt][nt][0] + accM[mt][nt][0];                     \
            float v1 = accC[mt][nt][1] + accM[mt][nt][1];                     \
            float v2 = accC[mt][nt][2] + accM[mt][nt][2];                     \
            float v3 = accC[mt][nt][3] + accM[mt][nt][3];                     \
            body                                                              \
        }                                                                     \
    }

// ---------------------------------------------------------------------------
// GRU GEMM: 1D grid, heavy-first order. corr_klo=1024 (stoch onehot).
// ---------------------------------------------------------------------------
__global__ void __launch_bounds__(256) gru_mma(const float* __restrict__ b_ih,
                                               const float* __restrict__ b_hh) {
    float accM[4][4][4] = {}, accC[4][4][4] = {};
    int bid = blockIdx.x;
    int bmT, bnT;
    if (bid < 128)      { bnT = bid & 7;             bmT = bid >> 3; }
    else if (bid < 192) { int r = bid - 128; bnT = 8 + (r & 3);  bmT = r >> 2; }
    else                { int r = bid - 192; bnT = 12 + (r & 3); bmT = r >> 2; }
    int bm = bmT * 128, bn = bnT * 128;
    int klo, khi;
    if (bnT < 8)       { klo = 0;    khi = KCAT; }
    else if (bnT < 12) { klo = 0;    khi = 1040; }
    else               { klo = 1024; khi = KCAT; }
    mma_core(gX0, gX1, gX2, KCAT, gW0, gW1, gW2, KCAT,
             klo, khi, 1024, bm, bn, accM, accC);

    auto wr = [&](int m, int n, float v) {
        if (n < 1024)      g_rz[m * 1024 + n] = v + b_ih[n] + b_hh[n];
        else if (n < 1536) g_xn[m * 512 + (n - 1024)] = v + b_ih[n];
        else               g_hn[m * 512 + (n - 1536)] = v + b_hh[(n - 1536) + 1024];
    };
    EPI_LOOP({
        wr(m0, n0, v0);
        wr(m0, n0 + 1, v1);
        wr(m0 + 8, n0, v2);
        wr(m0 + 8, n0 + 1, v3);
    })
}

// b1: split-K=2, partials (no bias) -> g_h1p[z]
__global__ void __launch_bounds__(256) b1_mma() {
    float accM[4][4][4] = {}, accC[4][4][4] = {};
    int bm = blockIdx.y * 128, bn = blockIdx.x * 128;
    int z = blockIdx.z;
    mma_core(gD0, gD1, gD2, 512, gP10, gP11, gP12, 512,
             z * 256, (z + 1) * 256, 0, bm, bn, accM, accC);
    float* dst = g_h1p + (size_t)z * B_ * 512;
    EPI_LOOP({
        dst[m0 * 512 + n0]           = v0;
        dst[m0 * 512 + n0 + 1]       = v1;
        dst[(m0 + 8) * 512 + n0]     = v2;
        dst[(m0 + 8) * 512 + n0 + 1] = v3;
    })
}

// ---------------------------------------------------------------------------
// c_mma: logits GEMM with FUSED gumbel-argmax sampling epilogue.
// Each warp's 32-wide n-tile is exactly one softmax group; each output row's
// 32 candidates live in one quad (lanes 4g..4g+3). Tie-break: lowest index
// (== jnp.argmax first-max). Writes onehot to out + gX0 stoch planes.
// ---------------------------------------------------------------------------
__global__ void __launch_bounds__(256) c_mma(const float* __restrict__ pb2,
                                             float* __restrict__ out, int t) {
    float accM[4][4][4] = {}, accC[4][4][4] = {};
    int bm = blockIdx.y * 128, bn = blockIdx.x * 128;
    mma_core(gH0, gH1, gH2, 512, gP20, gP21, gP22, 512,
             0, 512, 0, bm, bn, accM, accC);

    const int lane = threadIdx.x & 31;
    const int wm = ((threadIdx.x >> 5) >> 2) * 64;
    const int wn = ((threadIdx.x >> 5) & 3) * 32;
    const int g = lane >> 2, tig = lane & 3;
    const int gbase = bn + wn;                     // group base column (mult of 32)
    const float* gum_t = g_gum + (size_t)t * B_ * SC_;

    const __nv_bfloat16 zero = __float2bfloat16_rn(0.f);
    const __nv_bfloat16 one  = __float2bfloat16_rn(1.f);

#pragma unroll
    for (int mt = 0; mt < 4; mt++) {
        int mrow0 = bm + wm + mt * 16 + g;
#pragma unroll
        for (int half = 0; half < 2; half++) {
            int row = mrow0 + half * 8;
            const float* gr = gum_t + (size_t)row * SC_ + gbase;
            float best = -1e30f;
            int bi = 0;
            float lgv[4][2];
#pragma unroll
            for (int nt = 0; nt < 4; nt++) {
                int n0 = wn + nt * 8 + 2 * tig;    // col within this 128-tile? no:
                // n0 here is offset within group? gbase covers bn+wn; channel:
                int c0 = nt * 8 + 2 * tig;
#pragma unroll
                for (int j = 0; j < 2; j++) {
                    float lg = (accC[mt][nt][2 * half + j] + accM[mt][nt][2 * half + j])
                               + pb2[gbase + c0 + j];
                    lgv[nt][j] = lg;
                    float v = gr[c0 + j] + lg;     // gum + logit (same order as before)
                    int c = c0 + j;
                    if (v > best) { best = v; bi = c; }
                }
                (void)n0;
            }
#pragma unroll
            for (int d = 1; d <= 2; d <<= 1) {
                float ov = __shfl_xor_sync(0xffffffffu, best, d);
                int oi = __shfl_xor_sync(0xffffffffu, bi, d);
                if (ov > best || (ov == best && oi < bi)) { best = ov; bi = oi; }
            }
            float* os = out + ((size_t)t * B_ + row) * OUTW + 512 + gbase;
            __nv_bfloat16* xs = gX0 + (size_t)row * KCAT + gbase;
#pragma unroll
            for (int nt = 0; nt < 4; nt++) {
                int c0 = nt * 8 + 2 * tig;
#pragma unroll
                for (int j = 0; j < 2; j++) {
                    bool hit = (c0 + j == bi);
                    os[c0 + j] = hit ? 1.0f : 0.0f;
                    xs[c0 + j] = hit ? one : zero;
                }
            }
            (void)lgv;
        }
    }
}

// ---------------------------------------------------------------------------
// GRU gates (+ next-step action staging, moved from sample_kernel)
// ---------------------------------------------------------------------------
__global__ void gates_kernel(const float* __restrict__ act_seq,
                             float* __restrict__ out, int t) {
    int gid = blockIdx.x * blockDim.x + threadIdx.x;
    int b = gid >> 9, d = gid & 511;
    float sr = g_rz[b * 1024 + d];
    float sz = g_rz[b * 1024 + 512 + d];
    float xn = g_xn[b * 512 + d];
    float hn = g_hn[b * 512 + d];
    float h  = g_deter[b * 512 + d];
    float r = 1.f / (1.f + expf(-sr));
    float z = 1.f / (1.f + expf(-sz));
    float n = tanhf(xn + r * hn);
    float dn = (1.f - z) * n + z * h;
    g_deter[b * 512 + d] = dn;
    out[((size_t)t * B_ + b) * OUTW + d] = dn;
    __nv_bfloat16 p0, p1, p2;
    split3(dn, p0, p1, p2);
    int xk = b * KCAT + 1034 + d;
    gX0[xk] = p0; gX1[xk] = p1; gX2[xk] = p2;
    int dk = b * 512 + d;
    gD0[dk] = p0; gD1[dk] = p1; gD2[dk] = p2;
    if (t < H_ - 1 && d < ACT_) {
        float a = act_seq[(((size_t)(t + 1)) * B_ + b) * ACT_ + d];
        __nv_bfloat16 q0, q1, q2;
        split3(a, q0, q1, q2);
        int ak = b * KCAT + SC_ + d;
        gX0[ak] = q0; gX1[ak] = q1; gX2[ak] = q2;
    }
}

// ---------------------------------------------------------------------------
// LayerNorm + SiLU; sums split-K partials + bias (fixed RN order)
// ---------------------------------------------------------------------------
__global__ void ln_kernel(const float* __restrict__ pg,
                          const float* __restrict__ pbeta,
                          const float* __restrict__ pb1) {
    __shared__ float red[256];
    int b = blockIdx.x, tid = threadIdx.x;
    const float* x0 = g_h1p + b * 512;
    const float* x1 = g_h1p + (size_t)B_ * 512 + b * 512;
    float v0 = (x0[tid] + x1[tid]) + pb1[tid];
    float v1 = (x0[tid + 256] + x1[tid + 256]) + pb1[tid + 256];
    red[tid] = v0 + v1;
    __syncthreads();
    for (int s = 128; s > 0; s >>= 1) {
        if (tid < s) red[tid] += red[tid + s];
        __syncthreads();
    }
    float mean = red[0] * (1.f / 512.f);
    __syncthreads();
    float d0 = v0 - mean, d1 = v1 - mean;
    red[tid] = d0 * d0 + d1 * d1;
    __syncthreads();
    for (int s = 128; s > 0; s >>= 1) {
        if (tid < s) red[tid] += red[tid + s];
        __syncthreads();
    }
    float var = red[0] * (1.f / 512.f);
    float rstd = rsqrtf(var + 1e-5f);
    float y0 = d0 * rstd * pg[tid] + pbeta[tid];
    float y1 = d1 * rstd * pg[tid + 256] + pbeta[tid + 256];
    float s0 = y0 * (1.f / (1.f + expf(-y0)));
    float s1 = y1 * (1.f / (1.f + expf(-y1)));
    __nv_bfloat16 a, bb, c;
    split3(s0, a, bb, c);
    gH0[b * 512 + tid] = a; gH1[b * 512 + tid] = bb; gH2[b * 512 + tid] = c;
    split3(s1, a, bb, c);
    gH0[b * 512 + tid + 256] = a; gH1[b * 512 + tid + 256] = bb; gH2[b * 512 + tid + 256] = c;
}

// ---------------------------------------------------------------------------
// Host launcher
// ---------------------------------------------------------------------------
extern "C" void kernel_launch(void* const* d_in, const int* in_sizes, int n_in,
                              void* d_out, int out_size) {
    const float* act    = (const float*)d_in[0];
    const float* deter0 = (const float*)d_in[1];
    const float* stoch0 = (const float*)d_in[2];
    const float* W_ih   = (const float*)d_in[3];
    const float* b_ih   = (const float*)d_in[4];
    const float* W_hh   = (const float*)d_in[5];
    const float* b_hh   = (const float*)d_in[6];
    const float* pW1    = (const float*)d_in[7];
    const float* pb1    = (const float*)d_in[8];
    const float* pg     = (const float*)d_in[9];
    const float* pbeta  = (const float*)d_in[10];
    const float* pW2    = (const float*)d_in[11];
    const float* pb2    = (const float*)d_in[12];
    float* out = (float*)d_out;

    cudaFuncSetAttribute(gru_mma, cudaFuncAttributeMaxDynamicSharedMemorySize, SMEM_BYTES);
    cudaFuncSetAttribute(b1_mma,  cudaFuncAttributeMaxDynamicSharedMemorySize, SMEM_BYTES);
    cudaFuncSetAttribute(c_mma,   cudaFuncAttributeMaxDynamicSharedMemorySize, SMEM_BYTES);

    cudaStream_t st = cudaStreamPerThread;
    init_kernel<<<(B_ * KCAT + 255) / 256, 256, 0, st>>>(stoch0, act, deter0);
    wprep_kernel<<<(2048 * KCAT + 255) / 256, 256, 0, st>>>(W_ih, W_hh);
    pprep_kernel<<<((512 * 512 + 1024 * 512) + 255) / 256, 256, 0, st>>>(pW1, pW2);
    gumbel_prep<<<(int)(((size_t)H_ * B_ * SC_ + 255) / 256), 256, 0, st>>>();

    for (int t = 0; t < H_; t++) {
        gru_mma<<<256, 256, SMEM_BYTES, st>>>(b_ih, b_hh);
        gates_kernel<<<(B_ * DETER_) / 256, 256, 0, st>>>(act, out, t);
        b1_mma<<<dim3(4, 16, 2), 256, SMEM_BYTES, st>>>();
        ln_kernel<<<B_, 256, 0, st>>>(pg, pbeta, pb1);
        c_mma<<<dim3(8, 16), 256, SMEM_BYTES, st>>>(pb2, out, t);
    }
}

// round 14
// speedup vs baseline: 2.0541x; 1.0177x over previous
#include <cuda_runtime.h>
#include <cuda_bf16.h>
#include <cstdint>

// ---------------------------------------------------------------------------
// RSSM rollout: H=16 steps, B=2048
// R12: R11 (4752us) with frozen mma core +
//   - gumbel_prep: per-block key broadcast (halves threefry work), 2 values
//     per thread with float2 store  [bit-identical values]
//   - init/wprep: 2D grids, no integer div/mod   [identical stores]
// ---------------------------------------------------------------------------

#define B_       2048
#define DETER_   512
#define SC_      1024
#define ACT_     10
#define H_       16
#define KCAT     1552
#define OUTW     1536

#define KPAD     24
#define PLANE_ELT (128 * KPAD)
#define SMEM_HALF (6 * PLANE_ELT)
#define SMEM_BYTES (2 * SMEM_HALF * 2)   // 73728 B

// fp32 state
__device__ float g_deter[B_ * DETER_];
__device__ float g_rz[B_ * 1024];
__device__ float g_xn[B_ * DETER_];
__device__ float g_hn[B_ * DETER_];
__device__ float g_h1p[2 * B_ * DETER_];
__device__ float g_gum[(size_t)H_ * B_ * SC_];   // gumbel table

// bf16x3 planes
__device__ __nv_bfloat16 gW0[2048 * KCAT], gW1[2048 * KCAT], gW2[2048 * KCAT];
__device__ __nv_bfloat16 gX0[B_ * KCAT],  gX1[B_ * KCAT],  gX2[B_ * KCAT];
__device__ __nv_bfloat16 gD0[B_ * DETER_], gD1[B_ * DETER_], gD2[B_ * DETER_];
__device__ __nv_bfloat16 gH0[B_ * DETER_], gH1[B_ * DETER_], gH2[B_ * DETER_];
__device__ __nv_bfloat16 gP10[512 * 512],  gP11[512 * 512],  gP12[512 * 512];
__device__ __nv_bfloat16 gP20[1024 * 512], gP21[1024 * 512], gP22[1024 * 512];

// ---------------------------------------------------------------------------
// Threefry-2x32 (JAX schedule) — proven bit-exact, do not touch
// ---------------------------------------------------------------------------
__host__ __device__ __forceinline__ uint32_t rotl32(uint32_t v, int d) {
    return (v << d) | (v >> (32 - d));
}
__host__ __device__ __forceinline__ void threefry2x32(uint32_t k0, uint32_t k1,
                                                      uint32_t x0, uint32_t x1,
                                                      uint32_t& o0, uint32_t& o1) {
    uint32_t ks0 = k0, ks1 = k1, ks2 = k0 ^ k1 ^ 0x1BD11BDAu;
    x0 += ks0; x1 += ks1;
    x0 += x1; x1 = rotl32(x1, 13); x1 ^= x0;
    x0 += x1; x1 = rotl32(x1, 15); x1 ^= x0;
    x0 += x1; x1 = rotl32(x1, 26); x1 ^= x0;
    x0 += x1; x1 = rotl32(x1, 6);  x1 ^= x0;
    x0 += ks1; x1 += ks2 + 1u;
    x0 += x1; x1 = rotl32(x1, 17); x1 ^= x0;
    x0 += x1; x1 = rotl32(x1, 29); x1 ^= x0;
    x0 += x1; x1 = rotl32(x1, 16); x1 ^= x0;
    x0 += x1; x1 = rotl32(x1, 24); x1 ^= x0;
    x0 += ks2; x1 += ks0 + 2u;
    x0 += x1; x1 = rotl32(x1, 13); x1 ^= x0;
    x0 += x1; x1 = rotl32(x1, 15); x1 ^= x0;
    x0 += x1; x1 = rotl32(x1, 26); x1 ^= x0;
    x0 += x1; x1 = rotl32(x1, 6);  x1 ^= x0;
    x0 += ks0; x1 += ks1 + 3u;
    x0 += x1; x1 = rotl32(x1, 17); x1 ^= x0;
    x0 += x1; x1 = rotl32(x1, 29); x1 ^= x0;
    x0 += x1; x1 = rotl32(x1, 16); x1 ^= x0;
    x0 += x1; x1 = rotl32(x1, 24); x1 ^= x0;
    x0 += ks1; x1 += ks2 + 4u;
    x0 += x1; x1 = rotl32(x1, 13); x1 ^= x0;
    x0 += x1; x1 = rotl32(x1, 15); x1 ^= x0;
    x0 += x1; x1 = rotl32(x1, 26); x1 ^= x0;
    x0 += x1; x1 = rotl32(x1, 6);  x1 ^= x0;
    x0 += ks2; x1 += ks0 + 5u;
    o0 = x0; o1 = x1;
}

// exact 3-way bf16 split
__device__ __forceinline__ void split3(float v, __nv_bfloat16& b0,
                                       __nv_bfloat16& b1, __nv_bfloat16& b2) {
    b0 = __float2bfloat16_rn(v);
    float r = v - __bfloat162float(b0);
    b1 = __float2bfloat16_rn(r);
    float r2 = r - __bfloat162float(b1);
    b2 = __float2bfloat16_rn(r2);
}

// ---------------------------------------------------------------------------
// Prep kernels (run every call; div-free grids)
// ---------------------------------------------------------------------------
// grid: (B_), 256 threads; k strided
__global__ void init_kernel(const float* __restrict__ stoch0,
                            const float* __restrict__ act_seq,
                            const float* __restrict__ deter0) {
    int b = blockIdx.x;
    for (int k = threadIdx.x; k < KCAT; k += 256) {
        float v = 0.f;
        if (k < SC_)             v = stoch0[b * SC_ + k];
        else if (k < SC_ + ACT_) v = act_seq[b * ACT_ + (k - SC_)];
        else if (k < 1546)       v = deter0[b * DETER_ + (k - SC_ - ACT_)];
        int gid = b * KCAT + k;
        split3(v, gX0[gid], gX1[gid], gX2[gid]);
        if (k < DETER_) {
            float d = deter0[b * DETER_ + k];
            g_deter[b * DETER_ + k] = d;
            split3(d, gD0[b * DETER_ + k], gD1[b * DETER_ + k], gD2[b * DETER_ + k]);
        }
    }
}

// grid: (2048), 256 threads; k strided
__global__ void wprep_kernel(const float* __restrict__ W_ih,
                             const float* __restrict__ W_hh) {
    int r = blockIdx.x;
    for (int k = threadIdx.x; k < KCAT; k += 256) {
        float v = 0.f;
        if (r < 1024) {
            if (k < 1034)       v = W_ih[r * 1034 + k];
            else if (k < 1546)  v = W_hh[r * 512 + (k - 1034)];
        } else if (r < 1536) {
            if (k < 1034)       v = W_ih[r * 1034 + k];
        } else {
            if (k >= 1034 && k < 1546) v = W_hh[(r - 512) * 512 + (k - 1034)];
        }
        int gid = r * KCAT + k;
        split3(v, gW0[gid], gW1[gid], gW2[gid]);
    }
}

__global__ void pprep_kernel(const float* __restrict__ pW1,
                             const float* __restrict__ pW2) {
    int gid = blockIdx.x * blockDim.x + threadIdx.x;
    if (gid < 512 * 512) {
        split3(pW1[gid], gP10[gid], gP11[gid], gP12[gid]);
    } else if (gid < 512 * 512 + 1024 * 512) {
        int i = gid - 512 * 512;
        split3(pW2[i], gP20[i], gP21[i], gP22[i]);
    }
}

// gumbel table. grid: (4096, 16): y = t, x covers 2^21 values, 2 per thread.
// Per-block key broadcast (t constant within a block) halves threefry work.
// Values bit-identical to the R11 path.
__global__ void gumbel_prep() {
    __shared__ uint32_t sk[2];
    uint32_t t = blockIdx.y;
    if (threadIdx.x == 0) {
        uint32_t k0, k1;
        threefry2x32(0u, 42u, 0u, t, k0, k1);
        sk[0] = k0; sk[1] = k1;
    }
    __syncthreads();
    uint32_t k0 = sk[0], k1 = sk[1];
    uint32_t idx0 = (blockIdx.x * blockDim.x + threadIdx.x) * 2u;
    float2 out;
    {
        uint32_t o0, o1;
        threefry2x32(k0, k1, 0u, idx0, o0, o1);
        uint32_t bits = o0 ^ o1;
        float u = __uint_as_float((bits >> 9) | 0x3f800000u) - 1.0f;
        u = fmaxf(u, 1.1754943508222875e-38f);
        out.x = -logf(-logf(u));
    }
    {
        uint32_t o0, o1;
        threefry2x32(k0, k1, 0u, idx0 + 1u, o0, o1);
        uint32_t bits = o0 ^ o1;
        float u = __uint_as_float((bits >> 9) | 0x3f800000u) - 1.0f;
        u = fmaxf(u, 1.1754943508222875e-38f);
        out.y = -logf(-logf(u));
    }
    *(float2*)(g_gum + ((size_t)t << 21) + idx0) = out;
}

// ---------------------------------------------------------------------------
// MMA primitives
// ---------------------------------------------------------------------------
__device__ __forceinline__ void mma16816(float& c0, float& c1, float& c2, float& c3,
                                         uint32_t a0, uint32_t a1, uint32_t a2, uint32_t a3,
                                         uint32_t b0, uint32_t b1) {
    asm volatile(
        "mma.sync.aligned.m16n8k16.row.col.f32.bf16.bf16.f32 "
        "{%0,%1,%2,%3}, {%4,%5,%6,%7}, {%8,%9}, {%0,%1,%2,%3};"
        : "+f"(c0), "+f"(c1), "+f"(c2), "+f"(c3)
        : "r"(a0), "r"(a1), "r"(a2), "r"(a3), "r"(b0), "r"(b1));
}

__device__ __forceinline__ void ldm_x4(uint32_t& r0, uint32_t& r1,
                                       uint32_t& r2, uint32_t& r3, uint32_t addr) {
    asm volatile("ldmatrix.sync.aligned.m8n8.x4.shared.b16 {%0,%1,%2,%3}, [%4];"
                 : "=r"(r0), "=r"(r1), "=r"(r2), "=r"(r3) : "r"(addr));
}

// ---------------------------------------------------------------------------
// bf16x3 MMA core — EXACT R7 version (proven winner). Do not touch.
// ---------------------------------------------------------------------------
__device__ __forceinline__ void mma_core(
    const __nv_bfloat16* __restrict__ A0, const __nv_bfloat16* __restrict__ A1,
    const __nv_bfloat16* __restrict__ A2, int lda,
    const __nv_bfloat16* __restrict__ B0, const __nv_bfloat16* __restrict__ B1,
    const __nv_bfloat16* __restrict__ B2, int ldb,
    int klo, int khi, int corr_klo, int bm, int bn,
    float (&accM)[4][4][4], float (&accC)[4][4][4]) {
    extern __shared__ __nv_bfloat16 sm[];
    const int tid = threadIdx.x;
    const int lane = tid & 31;
    const int wm = ((tid >> 5) >> 2) * 64;
    const int wn = ((tid >> 5) & 3) * 32;
    const int g = lane >> 2, tig = lane & 3;
    const int lrow = tid >> 1, lhalf = tid & 1;

    const __nv_bfloat16* Ap[3] = {
        A0 + (size_t)(bm + lrow) * lda + lhalf * 8,
        A1 + (size_t)(bm + lrow) * lda + lhalf * 8,
        A2 + (size_t)(bm + lrow) * lda + lhalf * 8};
    const __nv_bfloat16* Bp[3] = {
        B0 + (size_t)(bn + lrow) * ldb + lhalf * 8,
        B1 + (size_t)(bn + lrow) * ldb + lhalf * 8,
        B2 + (size_t)(bn + lrow) * ldb + lhalf * 8};

    const uint32_t smbase = (uint32_t)__cvta_generic_to_shared(sm);
    const int nk = (khi - klo) >> 4;
    const int st_off = lrow * KPAD + lhalf * 8;

    uint4 pa[3], pb[3];
    bool gf = false;
    bool corrbuf[2] = {false, false};

    auto gload = [&](int k0) {
        gf = (k0 >= corr_klo);
        pa[0] = *(const uint4*)(Ap[0] + k0);
#pragma unroll
        for (int p = 0; p < 3; p++) pb[p] = *(const uint4*)(Bp[p] + k0);
        if (gf) {
            pa[1] = *(const uint4*)(Ap[1] + k0);
            pa[2] = *(const uint4*)(Ap[2] + k0);
        }
    };
    auto sstore = [&](int buf) {
        __nv_bfloat16* base = sm + buf * SMEM_HALF;
        *(uint4*)(base + 0 * PLANE_ELT + st_off) = pa[0];
#pragma unroll
        for (int p = 0; p < 3; p++)
            *(uint4*)(base + (3 + p) * PLANE_ELT + st_off) = pb[p];
        if (gf) {
            *(uint4*)(base + 1 * PLANE_ELT + st_off) = pa[1];
            *(uint4*)(base + 2 * PLANE_ELT + st_off) = pa[2];
        }
        corrbuf[buf] = gf;
    };
    auto compute = [&](int buf) {
        const bool corr = corrbuf[buf];
        const uint32_t abase = smbase + (uint32_t)(buf * SMEM_HALF) * 2;
        const __nv_bfloat16* sbb = sm + buf * SMEM_HALF + 3 * PLANE_ELT;
        uint32_t bf[3][4][2];
#pragma unroll
        for (int nt = 0; nt < 4; nt++) {
            const __nv_bfloat16* bq = sbb + (wn + nt * 8 + g) * KPAD + 2 * tig;
#pragma unroll
            for (int p = 0; p < 3; p++) {
                bf[p][nt][0] = *(const uint32_t*)(bq + p * PLANE_ELT);
                bf[p][nt][1] = *(const uint32_t*)(bq + p * PLANE_ELT + 8);
            }
        }
#pragma unroll
        for (int mt = 0; mt < 4; mt++) {
            uint32_t a0f[4], a1f[4], a2f[4];
            uint32_t arow = (uint32_t)((wm + mt * 16 + (lane & 15)) * KPAD * 2) +
                            (uint32_t)((lane >> 4) * 16);
            ldm_x4(a0f[0], a0f[1], a0f[2], a0f[3], abase + 0 * PLANE_ELT * 2 + arow);
            if (corr) {
                ldm_x4(a1f[0], a1f[1], a1f[2], a1f[3], abase + 1 * PLANE_ELT * 2 + arow);
                ldm_x4(a2f[0], a2f[1], a2f[2], a2f[3], abase + 2 * PLANE_ELT * 2 + arow);
            }
#pragma unroll
            for (int nt = 0; nt < 4; nt++) {
                float p0 = 0.f, p1 = 0.f, p2 = 0.f, p3 = 0.f;
                mma16816(p0, p1, p2, p3,
                         a0f[0], a0f[1], a0f[2], a0f[3],
                         bf[0][nt][0], bf[0][nt][1]);
                accM[mt][nt][0] += p0;
                accM[mt][nt][1] += p1;
                accM[mt][nt][2] += p2;
                accM[mt][nt][3] += p3;
                float* c = accC[mt][nt];
                if (corr) {
                    mma16816(c[0], c[1], c[2], c[3],
                             a2f[0], a2f[1], a2f[2], a2f[3],
                             bf[0][nt][0], bf[0][nt][1]);
                    mma16816(c[0], c[1], c[2], c[3],
                             a1f[0], a1f[1], a1f[2], a1f[3],
                             bf[1][nt][0], bf[1][nt][1]);
                }
                mma16816(c[0], c[1], c[2], c[3],
                         a0f[0], a0f[1], a0f[2], a0f[3],
                         bf[2][nt][0], bf[2][nt][1]);
                if (corr) {
                    mma16816(c[0], c[1], c[2], c[3],
                             a1f[0], a1f[1], a1f[2], a1f[3],
                             bf[0][nt][0], bf[0][nt][1]);
                }
                mma16816(c[0], c[1], c[2], c[3],
                         a0f[0], a0f[1], a0f[2], a0f[3],
                         bf[1][nt][0], bf[1][nt][1]);
            }
        }
    };

    gload(klo);
    sstore(0);
    __syncthreads();
    int cur = 0;
    for (int it = 1; it < nk; it++) {
        gload(klo + it * 16);
        compute(cur);
        sstore(cur ^ 1);
        __syncthreads();
        cur ^= 1;
    }
    compute(cur);
}

#define EPI_LOOP(body)                                                        \
    {                                                                         \
        const int lane = threadIdx.x & 31;                                    \
        const int wm = ((threadIdx.x >> 5) >> 2) * 64;                        \
        const int wn = ((threadIdx.x >> 5) & 3) * 32;                         \
        const int g = lane >> 2, tig = lane & 3;                              \
        _Pragma("unroll") for (int mt = 0; mt < 4; mt++)                      \
            _Pragma("unroll") for (int nt = 0; nt < 4; nt++) {                \
            int m0 = bm + wm + mt * 16 + g;                                   \
            int n0 = bn + wn + nt * 8 + 2 * tig;                              \
            float v0 = accC[mt][nt][0] + accM[mt][nt][0];                     \
            float v1 = accC[mt][nt][1] + accM[mt][nt][1];                     \
            float v2 = accC[mt][nt][2] + accM[mt][nt][2];                     \
            float v3 = accC[mt][nt][3] + accM[mt][nt][3];                     \
            body                                                              \
        }                                                                     \
    }

// ---------------------------------------------------------------------------
// GRU GEMM: 1D grid, heavy-first order. corr_klo=1024 (stoch onehot).
// ---------------------------------------------------------------------------
__global__ void __launch_bounds__(256) gru_mma(const float* __restrict__ b_ih,
                                               const float* __restrict__ b_hh) {
    float accM[4][4][4] = {}, accC[4][4][4] = {};
    int bid = blockIdx.x;
    int bmT, bnT;
    if (bid < 128)      { bnT = bid & 7;             bmT = bid >> 3; }
    else if (bid < 192) { int r = bid - 128; bnT = 8 + (r & 3);  bmT = r >> 2; }
    else                { int r = bid - 192; bnT = 12 + (r & 3); bmT = r >> 2; }
    int bm = bmT * 128, bn = bnT * 128;
    int klo, khi;
    if (bnT < 8)       { klo = 0;    khi = KCAT; }
    else if (bnT < 12) { klo = 0;    khi = 1040; }
    else               { klo = 1024; khi = KCAT; }
    mma_core(gX0, gX1, gX2, KCAT, gW0, gW1, gW2, KCAT,
             klo, khi, 1024, bm, bn, accM, accC);

    auto wr = [&](int m, int n, float v) {
        if (n < 1024)      g_rz[m * 1024 + n] = v + b_ih[n] + b_hh[n];
        else if (n < 1536) g_xn[m * 512 + (n - 1024)] = v + b_ih[n];
        else               g_hn[m * 512 + (n - 1536)] = v + b_hh[(n - 1536) + 1024];
    };
    EPI_LOOP({
        wr(m0, n0, v0);
        wr(m0, n0 + 1, v1);
        wr(m0 + 8, n0, v2);
        wr(m0 + 8, n0 + 1, v3);
    })
}

// b1: split-K=2, partials (no bias) -> g_h1p[z]
__global__ void __launch_bounds__(256) b1_mma() {
    float accM[4][4][4] = {}, accC[4][4][4] = {};
    int bm = blockIdx.y * 128, bn = blockIdx.x * 128;
    int z = blockIdx.z;
    mma_core(gD0, gD1, gD2, 512, gP10, gP11, gP12, 512,
             z * 256, (z + 1) * 256, 0, bm, bn, accM, accC);
    float* dst = g_h1p + (size_t)z * B_ * 512;
    EPI_LOOP({
        dst[m0 * 512 + n0]           = v0;
        dst[m0 * 512 + n0 + 1]       = v1;
        dst[(m0 + 8) * 512 + n0]     = v2;
        dst[(m0 + 8) * 512 + n0 + 1] = v3;
    })
}

// ---------------------------------------------------------------------------
// c_mma: logits GEMM with fused gumbel-argmax sampling epilogue (R11-proven).
// ---------------------------------------------------------------------------
__global__ void __launch_bounds__(256) c_mma(const float* __restrict__ pb2,
                                             float* __restrict__ out, int t) {
    float accM[4][4][4] = {}, accC[4][4][4] = {};
    int bm = blockIdx.y * 128, bn = blockIdx.x * 128;
    mma_core(gH0, gH1, gH2, 512, gP20, gP21, gP22, 512,
             0, 512, 0, bm, bn, accM, accC);

    const int lane = threadIdx.x & 31;
    const int wm = ((threadIdx.x >> 5) >> 2) * 64;
    const int wn = ((threadIdx.x >> 5) & 3) * 32;
    const int g = lane >> 2, tig = lane & 3;
    const int gbase = bn + wn;
    const float* gum_t = g_gum + (size_t)t * B_ * SC_;

    const __nv_bfloat16 zero = __float2bfloat16_rn(0.f);
    const __nv_bfloat16 one  = __float2bfloat16_rn(1.f);

#pragma unroll
    for (int mt = 0; mt < 4; mt++) {
        int mrow0 = bm + wm + mt * 16 + g;
#pragma unroll
        for (int half = 0; half < 2; half++) {
            int row = mrow0 + half * 8;
            const float* gr = gum_t + (size_t)row * SC_ + gbase;
            float best = -1e30f;
            int bi = 0;
#pragma unroll
            for (int nt = 0; nt < 4; nt++) {
                int c0 = nt * 8 + 2 * tig;
#pragma unroll
                for (int j = 0; j < 2; j++) {
                    float lg = (accC[mt][nt][2 * half + j] + accM[mt][nt][2 * half + j])
                               + pb2[gbase + c0 + j];
                    float v = gr[c0 + j] + lg;
                    if (v > best) { best = v; bi = c0 + j; }
                }
            }
#pragma unroll
            for (int d = 1; d <= 2; d <<= 1) {
                float ov = __shfl_xor_sync(0xffffffffu, best, d);
                int oi = __shfl_xor_sync(0xffffffffu, bi, d);
                if (ov > best || (ov == best && oi < bi)) { best = ov; bi = oi; }
            }
            float* os = out + ((size_t)t * B_ + row) * OUTW + 512 + gbase;
            __nv_bfloat16* xs = gX0 + (size_t)row * KCAT + gbase;
#pragma unroll
            for (int nt = 0; nt < 4; nt++) {
                int c0 = nt * 8 + 2 * tig;
#pragma unroll
                for (int j = 0; j < 2; j++) {
                    bool hit = (c0 + j == bi);
                    os[c0 + j] = hit ? 1.0f : 0.0f;
                    xs[c0 + j] = hit ? one : zero;
                }
            }
        }
    }
}

// ---------------------------------------------------------------------------
// GRU gates (+ next-step action staging)
// ---------------------------------------------------------------------------
__global__ void gates_kernel(const float* __restrict__ act_seq,
                             float* __restrict__ out, int t) {
    int gid = blockIdx.x * blockDim.x + threadIdx.x;
    int b = gid >> 9, d = gid & 511;
    float sr = g_rz[b * 1024 + d];
    float sz = g_rz[b * 1024 + 512 + d];
    float xn = g_xn[b * 512 + d];
    float hn = g_hn[b * 512 + d];
    float h  = g_deter[b * 512 + d];
    float r = 1.f / (1.f + expf(-sr));
    float z = 1.f / (1.f + expf(-sz));
    float n = tanhf(xn + r * hn);
    float dn = (1.f - z) * n + z * h;
    g_deter[b * 512 + d] = dn;
    out[((size_t)t * B_ + b) * OUTW + d] = dn;
    __nv_bfloat16 p0, p1, p2;
    split3(dn, p0, p1, p2);
    int xk = b * KCAT + 1034 + d;
    gX0[xk] = p0; gX1[xk] = p1; gX2[xk] = p2;
    int dk = b * 512 + d;
    gD0[dk] = p0; gD1[dk] = p1; gD2[dk] = p2;
    if (t < H_ - 1 && d < ACT_) {
        float a = act_seq[(((size_t)(t + 1)) * B_ + b) * ACT_ + d];
        __nv_bfloat16 q0, q1, q2;
        split3(a, q0, q1, q2);
        int ak = b * KCAT + SC_ + d;
        gX0[ak] = q0; gX1[ak] = q1; gX2[ak] = q2;
    }
}

// ---------------------------------------------------------------------------
// LayerNorm + SiLU; sums split-K partials + bias (fixed RN order)
// ---------------------------------------------------------------------------
__global__ void ln_kernel(const float* __restrict__ pg,
                          const float* __restrict__ pbeta,
                          const float* __restrict__ pb1) {
    __shared__ float red[256];
    int b = blockIdx.x, tid = threadIdx.x;
    const float* x0 = g_h1p + b * 512;
    const float* x1 = g_h1p + (size_t)B_ * 512 + b * 512;
    float v0 = (x0[tid] + x1[tid]) + pb1[tid];
    float v1 = (x0[tid + 256] + x1[tid + 256]) + pb1[tid + 256];
    red[tid] = v0 + v1;
    __syncthreads();
    for (int s = 128; s > 0; s >>= 1) {
        if (tid < s) red[tid] += red[tid + s];
        __syncthreads();
    }
    float mean = red[0] * (1.f / 512.f);
    __syncthreads();
    float d0 = v0 - mean, d1 = v1 - mean;
    red[tid] = d0 * d0 + d1 * d1;
    __syncthreads();
    for (int s = 128; s > 0; s >>= 1) {
        if (tid < s) red[tid] += red[tid + s];
        __syncthreads();
    }
    float var = red[0] * (1.f / 512.f);
    float rstd = rsqrtf(var + 1e-5f);
    float y0 = d0 * rstd * pg[tid] + pbeta[tid];
    float y1 = d1 * rstd * pg[tid + 256] + pbeta[tid + 256];
    float s0 = y0 * (1.f / (1.f + expf(-y0)));
    float s1 = y1 * (1.f / (1.f + expf(-y1)));
    __nv_bfloat16 a, bb, c;
    split3(s0, a, bb, c);
    gH0[b * 512 + tid] = a; gH1[b * 512 + tid] = bb; gH2[b * 512 + tid] = c;
    split3(s1, a, bb, c);
    gH0[b * 512 + tid + 256] = a; gH1[b * 512 + tid + 256] = bb; gH2[b * 512 + tid + 256] = c;
}

// ---------------------------------------------------------------------------
// Host launcher
// ---------------------------------------------------------------------------
extern "C" void kernel_launch(void* const* d_in, const int* in_sizes, int n_in,
                              void* d_out, int out_size) {
    const float* act    = (const float*)d_in[0];
    const float* deter0 = (const float*)d_in[1];
    const float* stoch0 = (const float*)d_in[2];
    const float* W_ih   = (const float*)d_in[3];
    const float* b_ih   = (const float*)d_in[4];
    const float* W_hh   = (const float*)d_in[5];
    const float* b_hh   = (const float*)d_in[6];
    const float* pW1    = (const float*)d_in[7];
    const float* pb1    = (const float*)d_in[8];
    const float* pg     = (const float*)d_in[9];
    const float* pbeta  = (const float*)d_in[10];
    const float* pW2    = (const float*)d_in[11];
    const float* pb2    = (const float*)d_in[12];
    float* out = (float*)d_out;

    cudaFuncSetAttribute(gru_mma, cudaFuncAttributeMaxDynamicSharedMemorySize, SMEM_BYTES);
    cudaFuncSetAttribute(b1_mma,  cudaFuncAttributeMaxDynamicSharedMemorySize, SMEM_BYTES);
    cudaFuncSetAttribute(c_mma,   cudaFuncAttributeMaxDynamicSharedMemorySize, SMEM_BYTES);

    cudaStream_t st = cudaStreamPerThread;
    init_kernel<<<B_, 256, 0, st>>>(stoch0, act, deter0);
    wprep_kernel<<<2048, 256, 0, st>>>(W_ih, W_hh);
    pprep_kernel<<<((512 * 512 + 1024 * 512) + 255) / 256, 256, 0, st>>>(pW1, pW2);
    gumbel_prep<<<dim3(4096, H_), 256, 0, st>>>();

    for (int t = 0; t < H_; t++) {
        gru_mma<<<256, 256, SMEM_BYTES, st>>>(b_ih, b_hh);
        gates_kernel<<<(B_ * DETER_) / 256, 256, 0, st>>>(act, out, t);
        b1_mma<<<dim3(4, 16, 2), 256, SMEM_BYTES, st>>>();
        ln_kernel<<<B_, 256, 0, st>>>(pg, pbeta, pb1);
        c_mma<<<dim3(8, 16), 256, SMEM_BYTES, st>>>(pb2, out, t);
    }
}

// round 15
// speedup vs baseline: 2.6036x; 1.2675x over previous
#include <cuda_runtime.h>
#include <cuda_bf16.h>
#include <cstdint>

// ---------------------------------------------------------------------------
// RSSM rollout: H=16 steps, B=2048
// R14: R12 (4670us, frozen mma core) + one-hot stoch GEMM replaced by gather:
//   - c_mma epilogue records argmax indices g_sidx (and drops stoch-plane writes)
//   - oh_gather computes P[b,n] = sum_s W_ih[n, 32s+idx[b,s]] from transposed W
//   - gru_mma(reduced=1) skips k<1024 for rz/xn and adds P in the epilogue
//   - t=0 uses the old full-K path (general stoch0)
// ---------------------------------------------------------------------------

#define B_       2048
#define DETER_   512
#define SC_      1024
#define ACT_     10
#define H_       16
#define KCAT     1552
#define OUTW     1536

#define KPAD     24
#define PLANE_ELT (128 * KPAD)
#define SMEM_HALF (6 * PLANE_ELT)
#define SMEM_BYTES (2 * SMEM_HALF * 2)   // 73728 B

// fp32 state
__device__ float g_deter[B_ * DETER_];
__device__ float g_rz[B_ * 1024];
__device__ float g_xn[B_ * DETER_];
__device__ float g_hn[B_ * DETER_];
__device__ float g_h1p[2 * B_ * DETER_];
__device__ float g_gum[(size_t)H_ * B_ * SC_];   // gumbel table
__device__ float g_Wt[1024 * 1536];              // W_ih^T for stoch region
__device__ float g_P[B_ * 1536];                 // one-hot gather partials
__device__ int   g_sidx[B_ * 32];                // argmax indices per group

// bf16x3 planes
__device__ __nv_bfloat16 gW0[2048 * KCAT], gW1[2048 * KCAT], gW2[2048 * KCAT];
__device__ __nv_bfloat16 gX0[B_ * KCAT],  gX1[B_ * KCAT],  gX2[B_ * KCAT];
__device__ __nv_bfloat16 gD0[B_ * DETER_], gD1[B_ * DETER_], gD2[B_ * DETER_];
__device__ __nv_bfloat16 gH0[B_ * DETER_], gH1[B_ * DETER_], gH2[B_ * DETER_];
__device__ __nv_bfloat16 gP10[512 * 512],  gP11[512 * 512],  gP12[512 * 512];
__device__ __nv_bfloat16 gP20[1024 * 512], gP21[1024 * 512], gP22[1024 * 512];

// ---------------------------------------------------------------------------
// Threefry-2x32 (JAX schedule) — proven bit-exact, do not touch
// ---------------------------------------------------------------------------
__host__ __device__ __forceinline__ uint32_t rotl32(uint32_t v, int d) {
    return (v << d) | (v >> (32 - d));
}
__host__ __device__ __forceinline__ void threefry2x32(uint32_t k0, uint32_t k1,
                                                      uint32_t x0, uint32_t x1,
                                                      uint32_t& o0, uint32_t& o1) {
    uint32_t ks0 = k0, ks1 = k1, ks2 = k0 ^ k1 ^ 0x1BD11BDAu;
    x0 += ks0; x1 += ks1;
    x0 += x1; x1 = rotl32(x1, 13); x1 ^= x0;
    x0 += x1; x1 = rotl32(x1, 15); x1 ^= x0;
    x0 += x1; x1 = rotl32(x1, 26); x1 ^= x0;
    x0 += x1; x1 = rotl32(x1, 6);  x1 ^= x0;
    x0 += ks1; x1 += ks2 + 1u;
    x0 += x1; x1 = rotl32(x1, 17); x1 ^= x0;
    x0 += x1; x1 = rotl32(x1, 29); x1 ^= x0;
    x0 += x1; x1 = rotl32(x1, 16); x1 ^= x0;
    x0 += x1; x1 = rotl32(x1, 24); x1 ^= x0;
    x0 += ks2; x1 += ks0 + 2u;
    x0 += x1; x1 = rotl32(x1, 13); x1 ^= x0;
    x0 += x1; x1 = rotl32(x1, 15); x1 ^= x0;
    x0 += x1; x1 = rotl32(x1, 26); x1 ^= x0;
    x0 += x1; x1 = rotl32(x1, 6);  x1 ^= x0;
    x0 += ks0; x1 += ks1 + 3u;
    x0 += x1; x1 = rotl32(x1, 17); x1 ^= x0;
    x0 += x1; x1 = rotl32(x1, 29); x1 ^= x0;
    x0 += x1; x1 = rotl32(x1, 16); x1 ^= x0;
    x0 += x1; x1 = rotl32(x1, 24); x1 ^= x0;
    x0 += ks1; x1 += ks2 + 4u;
    x0 += x1; x1 = rotl32(x1, 13); x1 ^= x0;
    x0 += x1; x1 = rotl32(x1, 15); x1 ^= x0;
    x0 += x1; x1 = rotl32(x1, 26); x1 ^= x0;
    x0 += x1; x1 = rotl32(x1, 6);  x1 ^= x0;
    x0 += ks2; x1 += ks0 + 5u;
    o0 = x0; o1 = x1;
}

// exact 3-way bf16 split
__device__ __forceinline__ void split3(float v, __nv_bfloat16& b0,
                                       __nv_bfloat16& b1, __nv_bfloat16& b2) {
    b0 = __float2bfloat16_rn(v);
    float r = v - __bfloat162float(b0);
    b1 = __float2bfloat16_rn(r);
    float r2 = r - __bfloat162float(b1);
    b2 = __float2bfloat16_rn(r2);
}

// ---------------------------------------------------------------------------
// Prep kernels
// ---------------------------------------------------------------------------
__global__ void init_kernel(const float* __restrict__ stoch0,
                            const float* __restrict__ act_seq,
                            const float* __restrict__ deter0) {
    int b = blockIdx.x;
    for (int k = threadIdx.x; k < KCAT; k += 256) {
        float v = 0.f;
        if (k < SC_)             v = stoch0[b * SC_ + k];
        else if (k < SC_ + ACT_) v = act_seq[b * ACT_ + (k - SC_)];
        else if (k < 1546)       v = deter0[b * DETER_ + (k - SC_ - ACT_)];
        int gid = b * KCAT + k;
        split3(v, gX0[gid], gX1[gid], gX2[gid]);
        if (k < DETER_) {
            float d = deter0[b * DETER_ + k];
            g_deter[b * DETER_ + k] = d;
            split3(d, gD0[b * DETER_ + k], gD1[b * DETER_ + k], gD2[b * DETER_ + k]);
        }
    }
}

__global__ void wprep_kernel(const float* __restrict__ W_ih,
                             const float* __restrict__ W_hh) {
    int r = blockIdx.x;
    for (int k = threadIdx.x; k < KCAT; k += 256) {
        float v = 0.f;
        if (r < 1024) {
            if (k < 1034)       v = W_ih[r * 1034 + k];
            else if (k < 1546)  v = W_hh[r * 512 + (k - 1034)];
        } else if (r < 1536) {
            if (k < 1034)       v = W_ih[r * 1034 + k];
        } else {
            if (k >= 1034 && k < 1546) v = W_hh[(r - 512) * 512 + (k - 1034)];
        }
        int gid = r * KCAT + k;
        split3(v, gW0[gid], gW1[gid], gW2[gid]);
    }
}

__global__ void pprep_kernel(const float* __restrict__ pW1,
                             const float* __restrict__ pW2) {
    int gid = blockIdx.x * blockDim.x + threadIdx.x;
    if (gid < 512 * 512) {
        split3(pW1[gid], gP10[gid], gP11[gid], gP12[gid]);
    } else if (gid < 512 * 512 + 1024 * 512) {
        int i = gid - 512 * 512;
        split3(pW2[i], gP20[i], gP21[i], gP22[i]);
    }
}

// transpose stoch columns of W_ih: g_Wt[k][n] = W_ih[n][k], k<1024, n<1536
__global__ void wt_prep(const float* __restrict__ W_ih) {
    int k = blockIdx.x;
    for (int n = threadIdx.x; n < 1536; n += 256)
        g_Wt[(size_t)k * 1536 + n] = W_ih[(size_t)n * 1034 + k];
}

// gumbel table (R12-proven, bit-identical values)
__global__ void gumbel_prep() {
    __shared__ uint32_t sk[2];
    uint32_t t = blockIdx.y;
    if (threadIdx.x == 0) {
        uint32_t k0, k1;
        threefry2x32(0u, 42u, 0u, t, k0, k1);
        sk[0] = k0; sk[1] = k1;
    }
    __syncthreads();
    uint32_t k0 = sk[0], k1 = sk[1];
    uint32_t idx0 = (blockIdx.x * blockDim.x + threadIdx.x) * 2u;
    float2 out;
    {
        uint32_t o0, o1;
        threefry2x32(k0, k1, 0u, idx0, o0, o1);
        uint32_t bits = o0 ^ o1;
        float u = __uint_as_float((bits >> 9) | 0x3f800000u) - 1.0f;
        u = fmaxf(u, 1.1754943508222875e-38f);
        out.x = -logf(-logf(u));
    }
    {
        uint32_t o0, o1;
        threefry2x32(k0, k1, 0u, idx0 + 1u, o0, o1);
        uint32_t bits = o0 ^ o1;
        float u = __uint_as_float((bits >> 9) | 0x3f800000u) - 1.0f;
        u = fmaxf(u, 1.1754943508222875e-38f);
        out.y = -logf(-logf(u));
    }
    *(float2*)(g_gum + ((size_t)t << 21) + idx0) = out;
}

// ---------------------------------------------------------------------------
// one-hot gather: P[b,n] = sum_{s<32} Wt[32s + idx[b,s]][n]
// grid (12, 256): x = n-tile(128), y = 8 b's per block (warp-per-b)
// ---------------------------------------------------------------------------
__global__ void __launch_bounds__(256) oh_gather() {
    int n0 = blockIdx.x * 128;
    int b  = blockIdx.y * 8 + (threadIdx.x >> 5);
    int lane = threadIdx.x & 31;
    const int* idx = g_sidx + b * 32;
    int nn = n0 + lane * 4;
    float4 acc = make_float4(0.f, 0.f, 0.f, 0.f);
#pragma unroll
    for (int s = 0; s < 32; s++) {
        int k = s * 32 + idx[s];                       // uniform per warp
        float4 w = *(const float4*)(g_Wt + (size_t)k * 1536 + nn);
        acc.x += w.x; acc.y += w.y; acc.z += w.z; acc.w += w.w;
    }
    *(float4*)(g_P + (size_t)b * 1536 + nn) = acc;
}

// ---------------------------------------------------------------------------
// MMA primitives
// ---------------------------------------------------------------------------
__device__ __forceinline__ void mma16816(float& c0, float& c1, float& c2, float& c3,
                                         uint32_t a0, uint32_t a1, uint32_t a2, uint32_t a3,
                                         uint32_t b0, uint32_t b1) {
    asm volatile(
        "mma.sync.aligned.m16n8k16.row.col.f32.bf16.bf16.f32 "
        "{%0,%1,%2,%3}, {%4,%5,%6,%7}, {%8,%9}, {%0,%1,%2,%3};"
        : "+f"(c0), "+f"(c1), "+f"(c2), "+f"(c3)
        : "r"(a0), "r"(a1), "r"(a2), "r"(a3), "r"(b0), "r"(b1));
}

__device__ __forceinline__ void ldm_x4(uint32_t& r0, uint32_t& r1,
                                       uint32_t& r2, uint32_t& r3, uint32_t addr) {
    asm volatile("ldmatrix.sync.aligned.m8n8.x4.shared.b16 {%0,%1,%2,%3}, [%4];"
                 : "=r"(r0), "=r"(r1), "=r"(r2), "=r"(r3) : "r"(addr));
}

// ---------------------------------------------------------------------------
// bf16x3 MMA core — EXACT R7 version (proven winner). Do not touch.
// ---------------------------------------------------------------------------
__device__ __forceinline__ void mma_core(
    const __nv_bfloat16* __restrict__ A0, const __nv_bfloat16* __restrict__ A1,
    const __nv_bfloat16* __restrict__ A2, int lda,
    const __nv_bfloat16* __restrict__ B0, const __nv_bfloat16* __restrict__ B1,
    const __nv_bfloat16* __restrict__ B2, int ldb,
    int klo, int khi, int corr_klo, int bm, int bn,
    float (&accM)[4][4][4], float (&accC)[4][4][4]) {
    extern __shared__ __nv_bfloat16 sm[];
    const int tid = threadIdx.x;
    const int lane = tid & 31;
    const int wm = ((tid >> 5) >> 2) * 64;
    const int wn = ((tid >> 5) & 3) * 32;
    const int g = lane >> 2, tig = lane & 3;
    const int lrow = tid >> 1, lhalf = tid & 1;

    const __nv_bfloat16* Ap[3] = {
        A0 + (size_t)(bm + lrow) * lda + lhalf * 8,
        A1 + (size_t)(bm + lrow) * lda + lhalf * 8,
        A2 + (size_t)(bm + lrow) * lda + lhalf * 8};
    const __nv_bfloat16* Bp[3] = {
        B0 + (size_t)(bn + lrow) * ldb + lhalf * 8,
        B1 + (size_t)(bn + lrow) * ldb + lhalf * 8,
        B2 + (size_t)(bn + lrow) * ldb + lhalf * 8};

    const uint32_t smbase = (uint32_t)__cvta_generic_to_shared(sm);
    const int nk = (khi - klo) >> 4;
    const int st_off = lrow * KPAD + lhalf * 8;

    uint4 pa[3], pb[3];
    bool gf = false;
    bool corrbuf[2] = {false, false};

    auto gload = [&](int k0) {
        gf = (k0 >= corr_klo);
        pa[0] = *(const uint4*)(Ap[0] + k0);
#pragma unroll
        for (int p = 0; p < 3; p++) pb[p] = *(const uint4*)(Bp[p] + k0);
        if (gf) {
            pa[1] = *(const uint4*)(Ap[1] + k0);
            pa[2] = *(const uint4*)(Ap[2] + k0);
        }
    };
    auto sstore = [&](int buf) {
        __nv_bfloat16* base = sm + buf * SMEM_HALF;
        *(uint4*)(base + 0 * PLANE_ELT + st_off) = pa[0];
#pragma unroll
        for (int p = 0; p < 3; p++)
            *(uint4*)(base + (3 + p) * PLANE_ELT + st_off) = pb[p];
        if (gf) {
            *(uint4*)(base + 1 * PLANE_ELT + st_off) = pa[1];
            *(uint4*)(base + 2 * PLANE_ELT + st_off) = pa[2];
        }
        corrbuf[buf] = gf;
    };
    auto compute = [&](int buf) {
        const bool corr = corrbuf[buf];
        const uint32_t abase = smbase + (uint32_t)(buf * SMEM_HALF) * 2;
        const __nv_bfloat16* sbb = sm + buf * SMEM_HALF + 3 * PLANE_ELT;
        uint32_t bf[3][4][2];
#pragma unroll
        for (int nt = 0; nt < 4; nt++) {
            const __nv_bfloat16* bq = sbb + (wn + nt * 8 + g) * KPAD + 2 * tig;
#pragma unroll
            for (int p = 0; p < 3; p++) {
                bf[p][nt][0] = *(const uint32_t*)(bq + p * PLANE_ELT);
                bf[p][nt][1] = *(const uint32_t*)(bq + p * PLANE_ELT + 8);
            }
        }
#pragma unroll
        for (int mt = 0; mt < 4; mt++) {
            uint32_t a0f[4], a1f[4], a2f[4];
            uint32_t arow = (uint32_t)((wm + mt * 16 + (lane & 15)) * KPAD * 2) +
                            (uint32_t)((lane >> 4) * 16);
            ldm_x4(a0f[0], a0f[1], a0f[2], a0f[3], abase + 0 * PLANE_ELT * 2 + arow);
            if (corr) {
                ldm_x4(a1f[0], a1f[1], a1f[2], a1f[3], abase + 1 * PLANE_ELT * 2 + arow);
                ldm_x4(a2f[0], a2f[1], a2f[2], a2f[3], abase + 2 * PLANE_ELT * 2 + arow);
            }
#pragma unroll
            for (int nt = 0; nt < 4; nt++) {
                float p0 = 0.f, p1 = 0.f, p2 = 0.f, p3 = 0.f;
                mma16816(p0, p1, p2, p3,
                         a0f[0], a0f[1], a0f[2], a0f[3],
                         bf[0][nt][0], bf[0][nt][1]);
                accM[mt][nt][0] += p0;
                accM[mt][nt][1] += p1;
                accM[mt][nt][2] += p2;
                accM[mt][nt][3] += p3;
                float* c = accC[mt][nt];
                if (corr) {
                    mma16816(c[0], c[1], c[2], c[3],
                             a2f[0], a2f[1], a2f[2], a2f[3],
                             bf[0][nt][0], bf[0][nt][1]);
                    mma16816(c[0], c[1], c[2], c[3],
                             a1f[0], a1f[1], a1f[2], a1f[3],
                             bf[1][nt][0], bf[1][nt][1]);
                }
                mma16816(c[0], c[1], c[2], c[3],
                         a0f[0], a0f[1], a0f[2], a0f[3],
                         bf[2][nt][0], bf[2][nt][1]);
                if (corr) {
                    mma16816(c[0], c[1], c[2], c[3],
                             a1f[0], a1f[1], a1f[2], a1f[3],
                             bf[0][nt][0], bf[0][nt][1]);
                }
                mma16816(c[0], c[1], c[2], c[3],
                         a0f[0], a0f[1], a0f[2], a0f[3],
                         bf[1][nt][0], bf[1][nt][1]);
            }
        }
    };

    gload(klo);
    sstore(0);
    __syncthreads();
    int cur = 0;
    for (int it = 1; it < nk; it++) {
        gload(klo + it * 16);
        compute(cur);
        sstore(cur ^ 1);
        __syncthreads();
        cur ^= 1;
    }
    compute(cur);
}

#define EPI_LOOP(body)                                                        \
    {                                                                         \
        const int lane = threadIdx.x & 31;                                    \
        const int wm = ((threadIdx.x >> 5) >> 2) * 64;                        \
        const int wn = ((threadIdx.x >> 5) & 3) * 32;                         \
        const int g = lane >> 2, tig = lane & 3;                              \
        _Pragma("unroll") for (int mt = 0; mt < 4; mt++)                      \
            _Pragma("unroll") for (int nt = 0; nt < 4; nt++) {                \
            int m0 = bm + wm + mt * 16 + g;                                   \
            int n0 = bn + wn + nt * 8 + 2 * tig;                              \
            float v0 = accC[mt][nt][0] + accM[mt][nt][0];                     \
            float v1 = accC[mt][nt][1] + accM[mt][nt][1];                     \
            float v2 = accC[mt][nt][2] + accM[mt][nt][2];                     \
            float v3 = accC[mt][nt][3] + accM[mt][nt][3];                     \
            body                                                              \
        }                                                                     \
    }

// ---------------------------------------------------------------------------
// GRU GEMM. reduced=0: full K (t=0). reduced=1: k>=1024 only for rz/xn,
// one-hot partials g_P added in the epilogue.
// ---------------------------------------------------------------------------
__global__ void __launch_bounds__(256) gru_mma(const float* __restrict__ b_ih,
                                               const float* __restrict__ b_hh,
                                               int reduced) {
    float accM[4][4][4] = {}, accC[4][4][4] = {};
    int bid = blockIdx.x;
    int bmT, bnT;
    if (bid < 128)      { bnT = bid & 7;             bmT = bid >> 3; }
    else if (bid < 192) { int r = bid - 128; bnT = 8 + (r & 3);  bmT = r >> 2; }
    else                { int r = bid - 192; bnT = 12 + (r & 3); bmT = r >> 2; }
    int bm = bmT * 128, bn = bnT * 128;
    int klo, khi;
    if (bnT < 8)       { klo = reduced ? 1024 : 0; khi = KCAT; }
    else if (bnT < 12) { klo = reduced ? 1024 : 0; khi = 1040; }
    else               { klo = 1024;               khi = KCAT; }
    mma_core(gX0, gX1, gX2, KCAT, gW0, gW1, gW2, KCAT,
             klo, khi, 1024, bm, bn, accM, accC);

    auto wr = [&](int m, int n, float v) {
        if (reduced && n < 1536) v += g_P[(size_t)m * 1536 + n];
        if (n < 1024)      g_rz[m * 1024 + n] = v + b_ih[n] + b_hh[n];
        else if (n < 1536) g_xn[m * 512 + (n - 1024)] = v + b_ih[n];
        else               g_hn[m * 512 + (n - 1536)] = v + b_hh[(n - 1536) + 1024];
    };
    EPI_LOOP({
        wr(m0, n0, v0);
        wr(m0, n0 + 1, v1);
        wr(m0 + 8, n0, v2);
        wr(m0 + 8, n0 + 1, v3);
    })
}

// b1: split-K=2, partials (no bias) -> g_h1p[z]
__global__ void __launch_bounds__(256) b1_mma() {
    float accM[4][4][4] = {}, accC[4][4][4] = {};
    int bm = blockIdx.y * 128, bn = blockIdx.x * 128;
    int z = blockIdx.z;
    mma_core(gD0, gD1, gD2, 512, gP10, gP11, gP12, 512,
             z * 256, (z + 1) * 256, 0, bm, bn, accM, accC);
    float* dst = g_h1p + (size_t)z * B_ * 512;
    EPI_LOOP({
        dst[m0 * 512 + n0]           = v0;
        dst[m0 * 512 + n0 + 1]       = v1;
        dst[(m0 + 8) * 512 + n0]     = v2;
        dst[(m0 + 8) * 512 + n0 + 1] = v3;
    })
}

// ---------------------------------------------------------------------------
// c_mma: logits GEMM + fused gumbel-argmax. Writes onehot to out and argmax
// index to g_sidx (consumed by next step's oh_gather).
// ---------------------------------------------------------------------------
__global__ void __launch_bounds__(256) c_mma(const float* __restrict__ pb2,
                                             float* __restrict__ out, int t) {
    float accM[4][4][4] = {}, accC[4][4][4] = {};
    int bm = blockIdx.y * 128, bn = blockIdx.x * 128;
    mma_core(gH0, gH1, gH2, 512, gP20, gP21, gP22, 512,
             0, 512, 0, bm, bn, accM, accC);

    const int lane = threadIdx.x & 31;
    const int wm = ((threadIdx.x >> 5) >> 2) * 64;
    const int wn = ((threadIdx.x >> 5) & 3) * 32;
    const int g = lane >> 2, tig = lane & 3;
    const int gbase = bn + wn;
    const float* gum_t = g_gum + (size_t)t * B_ * SC_;

#pragma unroll
    for (int mt = 0; mt < 4; mt++) {
        int mrow0 = bm + wm + mt * 16 + g;
#pragma unroll
        for (int half = 0; half < 2; half++) {
            int row = mrow0 + half * 8;
            const float* gr = gum_t + (size_t)row * SC_ + gbase;
            float best = -1e30f;
            int bi = 0;
#pragma unroll
            for (int nt = 0; nt < 4; nt++) {
                int c0 = nt * 8 + 2 * tig;
#pragma unroll
                for (int j = 0; j < 2; j++) {
                    float lg = (accC[mt][nt][2 * half + j] + accM[mt][nt][2 * half + j])
                               + pb2[gbase + c0 + j];
                    float v = gr[c0 + j] + lg;
                    if (v > best) { best = v; bi = c0 + j; }
                }
            }
#pragma unroll
            for (int d = 1; d <= 2; d <<= 1) {
                float ov = __shfl_xor_sync(0xffffffffu, best, d);
                int oi = __shfl_xor_sync(0xffffffffu, bi, d);
                if (ov > best || (ov == best && oi < bi)) { best = ov; bi = oi; }
            }
            if (tig == 0) g_sidx[row * 32 + (gbase >> 5)] = bi;
            float* os = out + ((size_t)t * B_ + row) * OUTW + 512 + gbase;
#pragma unroll
            for (int nt = 0; nt < 4; nt++) {
                int c0 = nt * 8 + 2 * tig;
#pragma unroll
                for (int j = 0; j < 2; j++)
                    os[c0 + j] = (c0 + j == bi) ? 1.0f : 0.0f;
            }
        }
    }
}

// ---------------------------------------------------------------------------
// GRU gates (+ next-step action staging)
// ---------------------------------------------------------------------------
__global__ void gates_kernel(const float* __restrict__ act_seq,
                             float* __restrict__ out, int t) {
    int gid = blockIdx.x * blockDim.x + threadIdx.x;
    int b = gid >> 9, d = gid & 511;
    float sr = g_rz[b * 1024 + d];
    float sz = g_rz[b * 1024 + 512 + d];
    float xn = g_xn[b * 512 + d];
    float hn = g_hn[b * 512 + d];
    float h  = g_deter[b * 512 + d];
    float r = 1.f / (1.f + expf(-sr));
    float z = 1.f / (1.f + expf(-sz));
    float n = tanhf(xn + r * hn);
    float dn = (1.f - z) * n + z * h;
    g_deter[b * 512 + d] = dn;
    out[((size_t)t * B_ + b) * OUTW + d] = dn;
    __nv_bfloat16 p0, p1, p2;
    split3(dn, p0, p1, p2);
    int xk = b * KCAT + 1034 + d;
    gX0[xk] = p0; gX1[xk] = p1; gX2[xk] = p2;
    int dk = b * 512 + d;
    gD0[dk] = p0; gD1[dk] = p1; gD2[dk] = p2;
    if (t < H_ - 1 && d < ACT_) {
        float a = act_seq[(((size_t)(t + 1)) * B_ + b) * ACT_ + d];
        __nv_bfloat16 q0, q1, q2;
        split3(a, q0, q1, q2);
        int ak = b * KCAT + SC_ + d;
        gX0[ak] = q0; gX1[ak] = q1; gX2[ak] = q2;
    }
}

// ---------------------------------------------------------------------------
// LayerNorm + SiLU; sums split-K partials + bias (fixed RN order)
// ---------------------------------------------------------------------------
__global__ void ln_kernel(const float* __restrict__ pg,
                          const float* __restrict__ pbeta,
                          const float* __restrict__ pb1) {
    __shared__ float red[256];
    int b = blockIdx.x, tid = threadIdx.x;
    const float* x0 = g_h1p + b * 512;
    const float* x1 = g_h1p + (size_t)B_ * 512 + b * 512;
    float v0 = (x0[tid] + x1[tid]) + pb1[tid];
    float v1 = (x0[tid + 256] + x1[tid + 256]) + pb1[tid + 256];
    red[tid] = v0 + v1;
    __syncthreads();
    for (int s = 128; s > 0; s >>= 1) {
        if (tid < s) red[tid] += red[tid + s];
        __syncthreads();
    }
    float mean = red[0] * (1.f / 512.f);
    __syncthreads();
    float d0 = v0 - mean, d1 = v1 - mean;
    red[tid] = d0 * d0 + d1 * d1;
    __syncthreads();
    for (int s = 128; s > 0; s >>= 1) {
        if (tid < s) red[tid] += red[tid + s];
        __syncthreads();
    }
    float var = red[0] * (1.f / 512.f);
    float rstd = rsqrtf(var + 1e-5f);
    float y0 = d0 * rstd * pg[tid] + pbeta[tid];
    float y1 = d1 * rstd * pg[tid + 256] + pbeta[tid + 256];
    float s0 = y0 * (1.f / (1.f + expf(-y0)));
    float s1 = y1 * (1.f / (1.f + expf(-y1)));
    __nv_bfloat16 a, bb, c;
    split3(s0, a, bb, c);
    gH0[b * 512 + tid] = a; gH1[b * 512 + tid] = bb; gH2[b * 512 + tid] = c;
    split3(s1, a, bb, c);
    gH0[b * 512 + tid + 256] = a; gH1[b * 512 + tid + 256] = bb; gH2[b * 512 + tid + 256] = c;
}

// ---------------------------------------------------------------------------
// Host launcher
// ---------------------------------------------------------------------------
extern "C" void kernel_launch(void* const* d_in, const int* in_sizes, int n_in,
                              void* d_out, int out_size) {
    const float* act    = (const float*)d_in[0];
    const float* deter0 = (const float*)d_in[1];
    const float* stoch0 = (const float*)d_in[2];
    const float* W_ih   = (const float*)d_in[3];
    const float* b_ih   = (const float*)d_in[4];
    const float* W_hh   = (const float*)d_in[5];
    const float* b_hh   = (const float*)d_in[6];
    const float* pW1    = (const float*)d_in[7];
    const float* pb1    = (const float*)d_in[8];
    const float* pg     = (const float*)d_in[9];
    const float* pbeta  = (const float*)d_in[10];
    const float* pW2    = (const float*)d_in[11];
    const float* pb2    = (const float*)d_in[12];
    float* out = (float*)d_out;

    cudaFuncSetAttribute(gru_mma, cudaFuncAttributeMaxDynamicSharedMemorySize, SMEM_BYTES);
    cudaFuncSetAttribute(b1_mma,  cudaFuncAttributeMaxDynamicSharedMemorySize, SMEM_BYTES);
    cudaFuncSetAttribute(c_mma,   cudaFuncAttributeMaxDynamicSharedMemorySize, SMEM_BYTES);

    cudaStream_t st = cudaStreamPerThread;
    init_kernel<<<B_, 256, 0, st>>>(stoch0, act, deter0);
    wprep_kernel<<<2048, 256, 0, st>>>(W_ih, W_hh);
    pprep_kernel<<<((512 * 512 + 1024 * 512) + 255) / 256, 256, 0, st>>>(pW1, pW2);
    wt_prep<<<1024, 256, 0, st>>>(W_ih);
    gumbel_prep<<<dim3(4096, H_), 256, 0, st>>>();

    for (int t = 0; t < H_; t++) {
        if (t > 0) {
            oh_gather<<<dim3(12, 256), 256, 0, st>>>();
            gru_mma<<<256, 256, SMEM_BYTES, st>>>(b_ih, b_hh, 1);
        } else {
            gru_mma<<<256, 256, SMEM_BYTES, st>>>(b_ih, b_hh, 0);
        }
        gates_kernel<<<(B_ * DETER_) / 256, 256, 0, st>>>(act, out, t);
        b1_mma<<<dim3(4, 16, 2), 256, SMEM_BYTES, st>>>();
        ln_kernel<<<B_, 256, 0, st>>>(pg, pbeta, pb1);
        c_mma<<<dim3(8, 16), 256, SMEM_BYTES, st>>>(pb2, out, t);
    }
}